// round 12
// baseline (speedup 1.0000x reference)
#include <cuda_runtime.h>
#include <cuda_bf16.h>

#define NNODES 50000
#define NEDGES 800000
#define DIM 128
#define NH 4
#define MAXDEG 128

// ---------------- scratch (device globals: no allocs allowed) ----------------
__device__ __align__(16) float g_q[NNODES * DIM];
__device__ __align__(16) float g_k[NNODES * DIM];
__device__ __align__(16) float g_v[NNODES * DIM];

__device__ int g_deg[NNODES];
__device__ int g_bucket[NNODES * MAXDEG];

__device__ __align__(16) __nv_bfloat16 g_ahi[NNODES * DIM];
__device__ __align__(16) __nv_bfloat16 g_alo[NNODES * DIM];
__device__ __align__(16) __nv_bfloat16 g_wThi[4 * DIM * DIM];
__device__ __align__(16) __nv_bfloat16 g_wTlo[4 * DIM * DIM];

// ---------------- zero degrees ----------------
__global__ __launch_bounds__(256) void k_zero() {
    int t = blockIdx.x * blockDim.x + threadIdx.x;
    if (t < NNODES) g_deg[t] = 0;
}

// ---------------- weight prep: split + transpose W[k][n] -> wT[w][n][k] ----------------
__global__ __launch_bounds__(256) void k_prep(const float* __restrict__ Wt,
                                              const float* __restrict__ Ws,
                                              const float* __restrict__ Wc,
                                              const float* __restrict__ Wout) {
    int t = blockIdx.x * blockDim.x + threadIdx.x;
    if (t >= 4 * DIM * DIM) return;
    int w = t >> 14;
    int idx = t & 16383;
    int k = idx >> 7;
    int n = idx & 127;
    const float* W = (w == 0) ? Wt : (w == 1) ? Ws : (w == 2) ? Wc : Wout;
    float v = W[k * DIM + n];
    __nv_bfloat16 h = __float2bfloat16_rn(v);
    g_wThi[(size_t)w * DIM * DIM + n * DIM + k] = h;
    g_wTlo[(size_t)w * DIM * DIM + n * DIM + k] = __float2bfloat16_rn(v - __bfloat162float(h));
}

// ---------------- bucket fill ----------------
__global__ __launch_bounds__(256) void k_fill(const int* __restrict__ ei) {
    int e = blockIdx.x * blockDim.x + threadIdx.x;
    if (e >= NEDGES) return;
    int src = ei[e];
    int dst = ei[NEDGES + e];
    int pos = atomicAdd(&g_deg[dst], 1);
    g_bucket[dst * MAXDEG + pos] = src;
}

// ---------------- fused scores + softmax + aggregation (one warp / dst) ----------------
__global__ __launch_bounds__(256) void k_fused() {
    int n = (blockIdx.x * blockDim.x + threadIdx.x) >> 5;
    if (n >= NNODES) return;
    int l = threadIdx.x & 31;
    int start = n * MAXDEG;
    int deg = g_deg[n];

    float4 qv = *(const float4*)(g_q + (size_t)n * DIM + (l << 2));
    float denom = 0.0f;
    float4 vacc = make_float4(0.f, 0.f, 0.f, 0.f);

    int j = 0;
    for (; j + 1 < deg; j += 2) {
        int s0 = g_bucket[start + j];
        int s1 = g_bucket[start + j + 1];
        float4 k0 = *(const float4*)(g_k + (size_t)s0 * DIM + (l << 2));
        float4 k1 = *(const float4*)(g_k + (size_t)s1 * DIM + (l << 2));
        float4 v0 = *(const float4*)(g_v + (size_t)s0 * DIM + (l << 2));
        float4 v1 = *(const float4*)(g_v + (size_t)s1 * DIM + (l << 2));
        float p0 = qv.x * k0.x + qv.y * k0.y + qv.z * k0.z + qv.w * k0.w;
        float p1 = qv.x * k1.x + qv.y * k1.y + qv.z * k1.z + qv.w * k1.w;
        p0 += __shfl_xor_sync(0xffffffffu, p0, 1);
        p1 += __shfl_xor_sync(0xffffffffu, p1, 1);
        p0 += __shfl_xor_sync(0xffffffffu, p0, 2);
        p1 += __shfl_xor_sync(0xffffffffu, p1, 2);
        p0 += __shfl_xor_sync(0xffffffffu, p0, 4);
        p1 += __shfl_xor_sync(0xffffffffu, p1, 4);
        float e0 = __expf(p0);
        float e1 = __expf(p1);
        denom += e0 + e1;
        vacc.x = fmaf(e0, v0.x, fmaf(e1, v1.x, vacc.x));
        vacc.y = fmaf(e0, v0.y, fmaf(e1, v1.y, vacc.y));
        vacc.z = fmaf(e0, v0.z, fmaf(e1, v1.z, vacc.z));
        vacc.w = fmaf(e0, v0.w, fmaf(e1, v1.w, vacc.w));
    }
    if (j < deg) {
        int s0 = g_bucket[start + j];
        float4 k0 = *(const float4*)(g_k + (size_t)s0 * DIM + (l << 2));
        float4 v0 = *(const float4*)(g_v + (size_t)s0 * DIM + (l << 2));
        float p0 = qv.x * k0.x + qv.y * k0.y + qv.z * k0.z + qv.w * k0.w;
        p0 += __shfl_xor_sync(0xffffffffu, p0, 1);
        p0 += __shfl_xor_sync(0xffffffffu, p0, 2);
        p0 += __shfl_xor_sync(0xffffffffu, p0, 4);
        float e0 = __expf(p0);
        denom += e0;
        vacc.x = fmaf(e0, v0.x, vacc.x);
        vacc.y = fmaf(e0, v0.y, vacc.y);
        vacc.z = fmaf(e0, v0.z, vacc.z);
        vacc.w = fmaf(e0, v0.w, vacc.w);
    }
    float inv = (deg > 0) ? __fdividef(1.0f, denom) : 0.0f;
    float o[4] = {vacc.x * inv, vacc.y * inv, vacc.z * inv, vacc.w * inv};
    __nv_bfloat16 hi[4], lo[4];
#pragma unroll
    for (int i = 0; i < 4; i++) {
        hi[i] = __float2bfloat16_rn(o[i]);
        lo[i] = __float2bfloat16_rn(o[i] - __bfloat162float(hi[i]));
    }
    *(uint2*)(g_ahi + (size_t)n * DIM + (l << 2)) = *(uint2*)hi;
    *(uint2*)(g_alo + (size_t)n * DIM + (l << 2)) = *(uint2*)lo;
}

// ---------------- split-bf16 mma.sync GEMM bits ----------------
#define SMEM_STRIDE 136
#define ROW_BYTES   (SMEM_STRIDE * 2)   // 272 -> LDSM conflict-free (bank step 4)

__device__ __forceinline__ void mma_bf16(float* c, const unsigned* a, unsigned b0, unsigned b1) {
    asm volatile(
        "mma.sync.aligned.m16n8k16.row.col.f32.bf16.bf16.f32 "
        "{%0,%1,%2,%3}, {%4,%5,%6,%7}, {%8,%9}, {%0,%1,%2,%3};"
        : "+f"(c[0]), "+f"(c[1]), "+f"(c[2]), "+f"(c[3])
        : "r"(a[0]), "r"(a[1]), "r"(a[2]), "r"(a[3]), "r"(b0), "r"(b1));
}

__device__ __forceinline__ void ldsm_x4(unsigned& r0, unsigned& r1, unsigned& r2, unsigned& r3,
                                        unsigned addr) {
    asm volatile("ldmatrix.sync.aligned.m8n8.x4.shared.b16 {%0,%1,%2,%3}, [%4];"
                 : "=r"(r0), "=r"(r1), "=r"(r2), "=r"(r3) : "r"(addr));
}

// ================= QKV GEMM: 256x128 CTA tile, 512 threads, warp tile 64x32 =================
// smem: A_HI@0 (69632), A_LO@69632, W_HI@139264 (34816), W_LO@174080 -> 208896 total
#define QK_AHI 0
#define QK_ALO 69632
#define QK_WHI 139264
#define QK_WLO 174080
#define QK_SMEM 208896

__global__ __launch_bounds__(512, 1) void k_mma_qkv(const float* __restrict__ x) {
    extern __shared__ char smem[];
    unsigned smem_u = (unsigned)__cvta_generic_to_shared(smem);
    int t = threadIdx.x;
    int mode = blockIdx.y;
    int row0 = blockIdx.x * 256;
    float* outp = (mode == 0) ? g_q : (mode == 1) ? g_k : g_v;

    // ---- load + split A tile (256 x 128): 2 threads/row, 64 cols each ----
    {
        int r = t >> 1;
        int c0 = (t & 1) * 64;
        int gr = row0 + r;
        char* dsthi = smem + QK_AHI + r * ROW_BYTES + c0 * 2;
        char* dstlo = smem + QK_ALO + r * ROW_BYTES + c0 * 2;
        if (gr < NNODES) {
            const float4* srcp = (const float4*)(x + (size_t)gr * DIM + c0);
#pragma unroll
            for (int i = 0; i < 16; i++) {
                float4 v = srcp[i];
                __nv_bfloat16 hi[4], lo[4];
                hi[0] = __float2bfloat16_rn(v.x); lo[0] = __float2bfloat16_rn(v.x - __bfloat162float(hi[0]));
                hi[1] = __float2bfloat16_rn(v.y); lo[1] = __float2bfloat16_rn(v.y - __bfloat162float(hi[1]));
                hi[2] = __float2bfloat16_rn(v.z); lo[2] = __float2bfloat16_rn(v.z - __bfloat162float(hi[2]));
                hi[3] = __float2bfloat16_rn(v.w); lo[3] = __float2bfloat16_rn(v.w - __bfloat162float(hi[3]));
                ((uint2*)dsthi)[i] = *(uint2*)hi;
                ((uint2*)dstlo)[i] = *(uint2*)lo;
            }
        } else {
            uint2 z = make_uint2(0, 0);
#pragma unroll
            for (int i = 0; i < 16; i++) { ((uint2*)dsthi)[i] = z; ((uint2*)dstlo)[i] = z; }
        }
    }
    // ---- W tiles (128 x 128 hi/lo, [n][k]): 4 threads/row, 32 cols each ----
    {
        const __nv_bfloat16* w_hi_g = g_wThi + (size_t)mode * DIM * DIM;
        const __nv_bfloat16* w_lo_g = g_wTlo + (size_t)mode * DIM * DIM;
        int r = t >> 2;
        int c0 = (t & 3) * 32;
        const uint4* wh = (const uint4*)(w_hi_g + (size_t)r * DIM + c0);
        const uint4* wl = (const uint4*)(w_lo_g + (size_t)r * DIM + c0);
        char* dwh = smem + QK_WHI + r * ROW_BYTES + c0 * 2;
        char* dwl = smem + QK_WLO + r * ROW_BYTES + c0 * 2;
#pragma unroll
        for (int i = 0; i < 4; i++) {
            ((uint4*)dwh)[i] = wh[i];
            ((uint4*)dwl)[i] = wl[i];
        }
    }
    __syncthreads();

    int warp = t >> 5;                 // 0..15
    int lane = t & 31;
    int g  = lane >> 2;
    int tg = lane & 3;
    int m_base = (warp >> 2) * 64;     // 0,64,128,192
    int n_base = (warp & 3) * 32;      // 0,32,64,96

    unsigned a_off = (unsigned)((m_base + (lane & 15)) * ROW_BYTES + ((lane >> 4) << 3) * 2);
    unsigned b_off = (unsigned)((n_base + (lane & 7) + ((lane >> 4) << 3)) * ROW_BYTES
                                + (((lane >> 3) & 1) << 3) * 2);

    float acc[4][4][4];
#pragma unroll
    for (int mi = 0; mi < 4; mi++)
#pragma unroll
        for (int ni = 0; ni < 4; ni++)
#pragma unroll
            for (int j = 0; j < 4; j++) acc[mi][ni][j] = 0.0f;

    // single-buffered frags: A 32 regs, B 16 regs
    unsigned A[32], B[16];
#pragma unroll
    for (int k0 = 0; k0 < 8; k0++) {
        unsigned kb = (unsigned)(k0 * 32);
#pragma unroll
        for (int mi = 0; mi < 4; mi++)
            ldsm_x4(A[mi * 4], A[mi * 4 + 1], A[mi * 4 + 2], A[mi * 4 + 3],
                    smem_u + QK_AHI + a_off + mi * 16 * ROW_BYTES + kb);
#pragma unroll
        for (int mi = 0; mi < 4; mi++)
            ldsm_x4(A[16 + mi * 4], A[16 + mi * 4 + 1], A[16 + mi * 4 + 2], A[16 + mi * 4 + 3],
                    smem_u + QK_ALO + a_off + mi * 16 * ROW_BYTES + kb);
        ldsm_x4(B[0], B[1], B[2], B[3],     smem_u + QK_WHI + b_off + kb);
        ldsm_x4(B[4], B[5], B[6], B[7],     smem_u + QK_WHI + b_off + 16 * ROW_BYTES + kb);
        ldsm_x4(B[8], B[9], B[10], B[11],   smem_u + QK_WLO + b_off + kb);
        ldsm_x4(B[12], B[13], B[14], B[15], smem_u + QK_WLO + b_off + 16 * ROW_BYTES + kb);

        // term-outer: 16 independent acc chains per term
#pragma unroll
        for (int ni = 0; ni < 4; ni++)
#pragma unroll
            for (int mi = 0; mi < 4; mi++)
                mma_bf16(acc[mi][ni], A + mi * 4, B[ni * 2], B[ni * 2 + 1]);           // hi*hi
#pragma unroll
        for (int ni = 0; ni < 4; ni++)
#pragma unroll
            for (int mi = 0; mi < 4; mi++)
                mma_bf16(acc[mi][ni], A + mi * 4, B[8 + ni * 2], B[8 + ni * 2 + 1]);   // hi*lo
#pragma unroll
        for (int ni = 0; ni < 4; ni++)
#pragma unroll
            for (int mi = 0; mi < 4; mi++)
                mma_bf16(acc[mi][ni], A + 16 + mi * 4, B[ni * 2], B[ni * 2 + 1]);      // lo*hi
    }

    // ---- epilogue ----
#pragma unroll
    for (int mi = 0; mi < 4; mi++) {
#pragma unroll
        for (int ni = 0; ni < 4; ni++) {
            int c = n_base + ni * 8 + 2 * tg;
            int r0 = row0 + m_base + mi * 16 + g;
            int r1 = r0 + 8;
            if (r0 < NNODES)
                *(float2*)(outp + (size_t)r0 * DIM + c) = make_float2(acc[mi][ni][0], acc[mi][ni][1]);
            if (r1 < NNODES)
                *(float2*)(outp + (size_t)r1 * DIM + c) = make_float2(acc[mi][ni][2], acc[mi][ni][3]);
        }
    }
}

// ================= output GEMM: 64-row tiles, (256,2) =================
#define A_HI_OFF 0
#define A_LO_OFF 17408
#define W_HI_OFF 34816
#define W_LO_OFF 69632
#define SMEM_TOTAL 104448

__device__ __forceinline__ void load_frags(unsigned* A, unsigned* B, unsigned smem_u,
                                           unsigned a_off, unsigned b_off, unsigned kb) {
    ldsm_x4(A[0], A[1], A[2], A[3],     smem_u + A_HI_OFF + a_off + kb);
    ldsm_x4(A[4], A[5], A[6], A[7],     smem_u + A_HI_OFF + a_off + 16 * ROW_BYTES + kb);
    ldsm_x4(A[8], A[9], A[10], A[11],   smem_u + A_LO_OFF + a_off + kb);
    ldsm_x4(A[12], A[13], A[14], A[15], smem_u + A_LO_OFF + a_off + 16 * ROW_BYTES + kb);
    ldsm_x4(B[0], B[1], B[2], B[3],     smem_u + W_HI_OFF + b_off + kb);
    ldsm_x4(B[4], B[5], B[6], B[7],     smem_u + W_HI_OFF + b_off + 16 * ROW_BYTES + kb);
    ldsm_x4(B[8], B[9], B[10], B[11],   smem_u + W_LO_OFF + b_off + kb);
    ldsm_x4(B[12], B[13], B[14], B[15], smem_u + W_LO_OFF + b_off + 16 * ROW_BYTES + kb);
}

__device__ __forceinline__ void frag_mma(float acc[2][4][4], const unsigned* A, const unsigned* B) {
#pragma unroll
    for (int ni = 0; ni < 4; ni++)
#pragma unroll
        for (int mi = 0; mi < 2; mi++)
            mma_bf16(acc[mi][ni], A + mi * 4, B[ni * 2], B[ni * 2 + 1]);
#pragma unroll
    for (int ni = 0; ni < 4; ni++)
#pragma unroll
        for (int mi = 0; mi < 2; mi++)
            mma_bf16(acc[mi][ni], A + mi * 4, B[8 + ni * 2], B[8 + ni * 2 + 1]);
#pragma unroll
    for (int ni = 0; ni < 4; ni++)
#pragma unroll
        for (int mi = 0; mi < 2; mi++)
            mma_bf16(acc[mi][ni], A + 8 + mi * 4, B[ni * 2], B[ni * 2 + 1]);
}

__global__ __launch_bounds__(256, 2) void k_mma_out(const float* __restrict__ x,
                                                    const float* __restrict__ bout,
                                                    float* __restrict__ dout) {
    extern __shared__ char smem[];
    unsigned smem_u = (unsigned)__cvta_generic_to_shared(smem);
    int t = threadIdx.x;
    int row0 = blockIdx.x * 64;

    {
        int r = t >> 2;
        int c0 = (t & 3) * 32;
        int gr = row0 + r;
        char* dsthi = smem + A_HI_OFF + r * ROW_BYTES + c0 * 2;
        char* dstlo = smem + A_LO_OFF + r * ROW_BYTES + c0 * 2;
        if (gr < NNODES) {
            const uint4* sh = (const uint4*)(g_ahi + (size_t)gr * DIM + c0);
            const uint4* sl = (const uint4*)(g_alo + (size_t)gr * DIM + c0);
#pragma unroll
            for (int i = 0; i < 4; i++) {
                ((uint4*)dsthi)[i] = sh[i];
                ((uint4*)dstlo)[i] = sl[i];
            }
        } else {
            uint4 z = make_uint4(0, 0, 0, 0);
#pragma unroll
            for (int i = 0; i < 4; i++) { ((uint4*)dsthi)[i] = z; ((uint4*)dstlo)[i] = z; }
        }
    }
    {
        const __nv_bfloat16* w_hi_g = g_wThi + (size_t)3 * DIM * DIM;
        const __nv_bfloat16* w_lo_g = g_wTlo + (size_t)3 * DIM * DIM;
        int r = t >> 1;
        int half = (t & 1) * 64;
        const uint4* wh = (const uint4*)(w_hi_g + (size_t)r * DIM + half);
        const uint4* wl = (const uint4*)(w_lo_g + (size_t)r * DIM + half);
        char* dwh = smem + W_HI_OFF + r * ROW_BYTES + half * 2;
        char* dwl = smem + W_LO_OFF + r * ROW_BYTES + half * 2;
#pragma unroll
        for (int i = 0; i < 8; i++) {
            ((uint4*)dwh)[i] = wh[i];
            ((uint4*)dwl)[i] = wl[i];
        }
    }
    __syncthreads();

    int warp = t >> 5;
    int lane = t & 31;
    int g  = lane >> 2;
    int tg = lane & 3;
    int m_base = (warp >> 2) * 32;
    int n_base = (warp & 3) * 32;

    unsigned a_off = (unsigned)((m_base + (lane & 15)) * ROW_BYTES + ((lane >> 4) << 3) * 2);
    unsigned b_off = (unsigned)((n_base + (lane & 7) + ((lane >> 4) << 3)) * ROW_BYTES
                                + (((lane >> 3) & 1) << 3) * 2);

    float acc[2][4][4];
#pragma unroll
    for (int mi = 0; mi < 2; mi++)
#pragma unroll
        for (int ni = 0; ni < 4; ni++)
#pragma unroll
            for (int j = 0; j < 4; j++) acc[mi][ni][j] = 0.0f;

    unsigned Af[2][16], Bf[2][16];
    load_frags(Af[0], Bf[0], smem_u, a_off, b_off, 0);
#pragma unroll
    for (int k0 = 0; k0 < 8; k0++) {
        int cur = k0 & 1;
        if (k0 < 7)
            load_frags(Af[cur ^ 1], Bf[cur ^ 1], smem_u, a_off, b_off, (unsigned)((k0 + 1) * 32));
        frag_mma(acc, Af[cur], Bf[cur]);
    }

#pragma unroll
    for (int mi = 0; mi < 2; mi++) {
#pragma unroll
        for (int ni = 0; ni < 4; ni++) {
            int c = n_base + ni * 8 + 2 * tg;
            int r0 = row0 + m_base + mi * 16 + g;
            int r1 = r0 + 8;
            float2 b = *(const float2*)(bout + c);
            if (r0 < NNODES) {
                float2 xr = *(const float2*)(x + (size_t)r0 * DIM + c);
                float2 v0;
                v0.x = fmaxf(acc[mi][ni][0] + b.x, 0.0f) + xr.x;
                v0.y = fmaxf(acc[mi][ni][1] + b.y, 0.0f) + xr.y;
                *(float2*)(dout + (size_t)r0 * DIM + c) = v0;
            }
            if (r1 < NNODES) {
                float2 xr = *(const float2*)(x + (size_t)r1 * DIM + c);
                float2 v1;
                v1.x = fmaxf(acc[mi][ni][2] + b.x, 0.0f) + xr.x;
                v1.y = fmaxf(acc[mi][ni][3] + b.y, 0.0f) + xr.y;
                *(float2*)(dout + (size_t)r1 * DIM + c) = v1;
            }
        }
    }
}

// ---------------- launch ----------------
extern "C" void kernel_launch(void* const* d_in, const int* in_sizes, int n_in,
                              void* d_out, int out_size) {
    const float* x      = (const float*)d_in[0];
    const int* ei       = (const int*)d_in[1];
    const float* Wt     = (const float*)d_in[2];
    const float* Ws     = (const float*)d_in[3];
    const float* Wc     = (const float*)d_in[4];
    const float* Wout   = (const float*)d_in[5];
    const float* bout   = (const float*)d_in[6];
    float* out          = (float*)d_out;

    static bool configured = false;
    if (!configured) {
        cudaFuncSetAttribute(k_mma_qkv, cudaFuncAttributeMaxDynamicSharedMemorySize, QK_SMEM);
        cudaFuncSetAttribute(k_mma_out, cudaFuncAttributeMaxDynamicSharedMemorySize, SMEM_TOTAL);
        configured = true;
    }

    // profiled launch = index 3 -> k_mma_qkv
    k_zero<<<(NNODES + 255) / 256, 256>>>();                         // 0
    k_prep<<<(4 * DIM * DIM + 255) / 256, 256>>>(Wt, Ws, Wc, Wout);  // 1
    k_fill<<<(NEDGES + 255) / 256, 256>>>(ei);                       // 2
    dim3 gq((NNODES + 255) / 256, 3);
    k_mma_qkv<<<gq, 512, QK_SMEM>>>(x);                              // 3 <- profiled
    k_fused<<<(NNODES * 32 + 255) / 256, 256>>>();                   // 4
    k_mma_out<<<(NNODES + 63) / 64, 256, SMEM_TOTAL>>>(x, bout, out); // 5
}

// round 13
// speedup vs baseline: 1.0322x; 1.0322x over previous
#include <cuda_runtime.h>
#include <cuda_bf16.h>

#define NNODES 50000
#define NEDGES 800000
#define DIM 128
#define NH 4
#define MAXDEG 128

// ---------------- scratch (device globals: no allocs allowed) ----------------
__device__ __align__(16) float g_q[NNODES * DIM];
__device__ __align__(16) float g_k[NNODES * DIM];
__device__ __align__(16) float g_v[NNODES * DIM];

__device__ int g_deg[NNODES];
__device__ int g_bucket[NNODES * MAXDEG];

__device__ __align__(16) __nv_bfloat16 g_ahi[NNODES * DIM];
__device__ __align__(16) __nv_bfloat16 g_alo[NNODES * DIM];
__device__ __align__(16) __nv_bfloat16 g_wThi[4 * DIM * DIM];
__device__ __align__(16) __nv_bfloat16 g_wTlo[4 * DIM * DIM];

// ---------------- prep: zero degrees + split/transpose weights ----------------
__global__ __launch_bounds__(256) void k_prep(const float* __restrict__ Wt,
                                              const float* __restrict__ Ws,
                                              const float* __restrict__ Wc,
                                              const float* __restrict__ Wout) {
    int t = blockIdx.x * blockDim.x + threadIdx.x;
    if (t < NNODES) g_deg[t] = 0;
    if (t < 4 * DIM * DIM) {
        int w = t >> 14;
        int idx = t & 16383;
        int k = idx >> 7;
        int n = idx & 127;
        const float* W = (w == 0) ? Wt : (w == 1) ? Ws : (w == 2) ? Wc : Wout;
        float v = W[k * DIM + n];
        __nv_bfloat16 h = __float2bfloat16_rn(v);
        g_wThi[(size_t)w * DIM * DIM + n * DIM + k] = h;
        g_wTlo[(size_t)w * DIM * DIM + n * DIM + k] = __float2bfloat16_rn(v - __bfloat162float(h));
    }
}

// ---------------- bucket fill ----------------
__global__ __launch_bounds__(256) void k_fill(const int* __restrict__ ei) {
    int e = blockIdx.x * blockDim.x + threadIdx.x;
    if (e >= NEDGES) return;
    int src = ei[e];
    int dst = ei[NEDGES + e];
    int pos = atomicAdd(&g_deg[dst], 1);
    g_bucket[dst * MAXDEG + pos] = src;
}

// ---------------- fused scores + softmax + aggregation (one warp / dst) ----------------
// 4-edge unroll: four independent load/shfl/exp chains per iteration
__global__ __launch_bounds__(256) void k_fused() {
    int n = (blockIdx.x * blockDim.x + threadIdx.x) >> 5;
    if (n >= NNODES) return;
    int l = threadIdx.x & 31;
    int start = n * MAXDEG;
    int deg = g_deg[n];

    float4 qv = *(const float4*)(g_q + (size_t)n * DIM + (l << 2));
    float denom = 0.0f;
    float4 vacc = make_float4(0.f, 0.f, 0.f, 0.f);

    int j = 0;
    for (; j + 3 < deg; j += 4) {
        int s0 = g_bucket[start + j];
        int s1 = g_bucket[start + j + 1];
        int s2 = g_bucket[start + j + 2];
        int s3 = g_bucket[start + j + 3];
        float4 k0 = *(const float4*)(g_k + (size_t)s0 * DIM + (l << 2));
        float4 k1 = *(const float4*)(g_k + (size_t)s1 * DIM + (l << 2));
        float4 k2 = *(const float4*)(g_k + (size_t)s2 * DIM + (l << 2));
        float4 k3 = *(const float4*)(g_k + (size_t)s3 * DIM + (l << 2));
        float4 v0 = *(const float4*)(g_v + (size_t)s0 * DIM + (l << 2));
        float4 v1 = *(const float4*)(g_v + (size_t)s1 * DIM + (l << 2));
        float4 v2 = *(const float4*)(g_v + (size_t)s2 * DIM + (l << 2));
        float4 v3 = *(const float4*)(g_v + (size_t)s3 * DIM + (l << 2));
        float p0 = qv.x * k0.x + qv.y * k0.y + qv.z * k0.z + qv.w * k0.w;
        float p1 = qv.x * k1.x + qv.y * k1.y + qv.z * k1.z + qv.w * k1.w;
        float p2 = qv.x * k2.x + qv.y * k2.y + qv.z * k2.z + qv.w * k2.w;
        float p3 = qv.x * k3.x + qv.y * k3.y + qv.z * k3.z + qv.w * k3.w;
        p0 += __shfl_xor_sync(0xffffffffu, p0, 1);
        p1 += __shfl_xor_sync(0xffffffffu, p1, 1);
        p2 += __shfl_xor_sync(0xffffffffu, p2, 1);
        p3 += __shfl_xor_sync(0xffffffffu, p3, 1);
        p0 += __shfl_xor_sync(0xffffffffu, p0, 2);
        p1 += __shfl_xor_sync(0xffffffffu, p1, 2);
        p2 += __shfl_xor_sync(0xffffffffu, p2, 2);
        p3 += __shfl_xor_sync(0xffffffffu, p3, 2);
        p0 += __shfl_xor_sync(0xffffffffu, p0, 4);
        p1 += __shfl_xor_sync(0xffffffffu, p1, 4);
        p2 += __shfl_xor_sync(0xffffffffu, p2, 4);
        p3 += __shfl_xor_sync(0xffffffffu, p3, 4);
        float e0 = __expf(p0);
        float e1 = __expf(p1);
        float e2 = __expf(p2);
        float e3 = __expf(p3);
        denom += (e0 + e1) + (e2 + e3);
        vacc.x = fmaf(e0, v0.x, fmaf(e1, v1.x, fmaf(e2, v2.x, fmaf(e3, v3.x, vacc.x))));
        vacc.y = fmaf(e0, v0.y, fmaf(e1, v1.y, fmaf(e2, v2.y, fmaf(e3, v3.y, vacc.y))));
        vacc.z = fmaf(e0, v0.z, fmaf(e1, v1.z, fmaf(e2, v2.z, fmaf(e3, v3.z, vacc.z))));
        vacc.w = fmaf(e0, v0.w, fmaf(e1, v1.w, fmaf(e2, v2.w, fmaf(e3, v3.w, vacc.w))));
    }
    for (; j < deg; j++) {
        int s0 = g_bucket[start + j];
        float4 k0 = *(const float4*)(g_k + (size_t)s0 * DIM + (l << 2));
        float4 v0 = *(const float4*)(g_v + (size_t)s0 * DIM + (l << 2));
        float p0 = qv.x * k0.x + qv.y * k0.y + qv.z * k0.z + qv.w * k0.w;
        p0 += __shfl_xor_sync(0xffffffffu, p0, 1);
        p0 += __shfl_xor_sync(0xffffffffu, p0, 2);
        p0 += __shfl_xor_sync(0xffffffffu, p0, 4);
        float e0 = __expf(p0);
        denom += e0;
        vacc.x = fmaf(e0, v0.x, vacc.x);
        vacc.y = fmaf(e0, v0.y, vacc.y);
        vacc.z = fmaf(e0, v0.z, vacc.z);
        vacc.w = fmaf(e0, v0.w, vacc.w);
    }
    float inv = (deg > 0) ? __fdividef(1.0f, denom) : 0.0f;
    float o[4] = {vacc.x * inv, vacc.y * inv, vacc.z * inv, vacc.w * inv};
    __nv_bfloat16 hi[4], lo[4];
#pragma unroll
    for (int i = 0; i < 4; i++) {
        hi[i] = __float2bfloat16_rn(o[i]);
        lo[i] = __float2bfloat16_rn(o[i] - __bfloat162float(hi[i]));
    }
    *(uint2*)(g_ahi + (size_t)n * DIM + (l << 2)) = *(uint2*)hi;
    *(uint2*)(g_alo + (size_t)n * DIM + (l << 2)) = *(uint2*)lo;
}

// ---------------- split-bf16 mma.sync GEMM bits ----------------
#define SMEM_STRIDE 136
#define ROW_BYTES   (SMEM_STRIDE * 2)   // 272 -> LDSM conflict-free (bank step 4)

__device__ __forceinline__ void mma_bf16(float* c, const unsigned* a, unsigned b0, unsigned b1) {
    asm volatile(
        "mma.sync.aligned.m16n8k16.row.col.f32.bf16.bf16.f32 "
        "{%0,%1,%2,%3}, {%4,%5,%6,%7}, {%8,%9}, {%0,%1,%2,%3};"
        : "+f"(c[0]), "+f"(c[1]), "+f"(c[2]), "+f"(c[3])
        : "r"(a[0]), "r"(a[1]), "r"(a[2]), "r"(a[3]), "r"(b0), "r"(b1));
}

__device__ __forceinline__ void ldsm_x4(unsigned& r0, unsigned& r1, unsigned& r2, unsigned& r3,
                                        unsigned addr) {
    asm volatile("ldmatrix.sync.aligned.m8n8.x4.shared.b16 {%0,%1,%2,%3}, [%4];"
                 : "=r"(r0), "=r"(r1), "=r"(r2), "=r"(r3) : "r"(addr));
}

// ================= QKV GEMM: 128-row CTA tile, 512 threads, warp tile 32x32 =================
// smem: A_HI@0, A_LO@34816, W_HI@69632, W_LO@104448 -> 139264 total, 1 CTA/SM, 16 warps
#define QK_AHI 0
#define QK_ALO 34816
#define QK_WHI 69632
#define QK_WLO 104448
#define QK_SMEM 139264

__device__ __forceinline__ void qkv_load_frags(unsigned* A, unsigned* B, unsigned smem_u,
                                               unsigned a_off, unsigned b_off, unsigned kb) {
    ldsm_x4(A[0], A[1], A[2], A[3],     smem_u + QK_AHI + a_off + kb);
    ldsm_x4(A[4], A[5], A[6], A[7],     smem_u + QK_AHI + a_off + 16 * ROW_BYTES + kb);
    ldsm_x4(A[8], A[9], A[10], A[11],   smem_u + QK_ALO + a_off + kb);
    ldsm_x4(A[12], A[13], A[14], A[15], smem_u + QK_ALO + a_off + 16 * ROW_BYTES + kb);
    ldsm_x4(B[0], B[1], B[2], B[3],     smem_u + QK_WHI + b_off + kb);
    ldsm_x4(B[4], B[5], B[6], B[7],     smem_u + QK_WHI + b_off + 16 * ROW_BYTES + kb);
    ldsm_x4(B[8], B[9], B[10], B[11],   smem_u + QK_WLO + b_off + kb);
    ldsm_x4(B[12], B[13], B[14], B[15], smem_u + QK_WLO + b_off + 16 * ROW_BYTES + kb);
}

__device__ __forceinline__ void qkv_frag_mma(float acc[2][4][4], const unsigned* A, const unsigned* B) {
#pragma unroll
    for (int ni = 0; ni < 4; ni++)
#pragma unroll
        for (int mi = 0; mi < 2; mi++)
            mma_bf16(acc[mi][ni], A + mi * 4, B[ni * 2], B[ni * 2 + 1]);            // hi*hi
#pragma unroll
    for (int ni = 0; ni < 4; ni++)
#pragma unroll
        for (int mi = 0; mi < 2; mi++)
            mma_bf16(acc[mi][ni], A + mi * 4, B[8 + ni * 2], B[8 + ni * 2 + 1]);    // hi*lo
#pragma unroll
    for (int ni = 0; ni < 4; ni++)
#pragma unroll
        for (int mi = 0; mi < 2; mi++)
            mma_bf16(acc[mi][ni], A + 8 + mi * 4, B[ni * 2], B[ni * 2 + 1]);        // lo*hi
}

__global__ __launch_bounds__(512, 1) void k_mma_qkv(const float* __restrict__ x) {
    extern __shared__ char smem[];
    unsigned smem_u = (unsigned)__cvta_generic_to_shared(smem);
    int t = threadIdx.x;
    int mode = blockIdx.y;
    int row0 = blockIdx.x * 128;
    float* outp = (mode == 0) ? g_q : (mode == 1) ? g_k : g_v;

    // ---- load + split A tile (128 x 128): 4 threads/row ----
    {
        int r = t >> 2;
        int c0 = (t & 3) * 32;
        int gr = row0 + r;
        char* dsthi = smem + QK_AHI + r * ROW_BYTES + c0 * 2;
        char* dstlo = smem + QK_ALO + r * ROW_BYTES + c0 * 2;
        if (gr < NNODES) {
            const float4* srcp = (const float4*)(x + (size_t)gr * DIM + c0);
#pragma unroll
            for (int i = 0; i < 8; i++) {
                float4 v = srcp[i];
                __nv_bfloat16 hi[4], lo[4];
                hi[0] = __float2bfloat16_rn(v.x); lo[0] = __float2bfloat16_rn(v.x - __bfloat162float(hi[0]));
                hi[1] = __float2bfloat16_rn(v.y); lo[1] = __float2bfloat16_rn(v.y - __bfloat162float(hi[1]));
                hi[2] = __float2bfloat16_rn(v.z); lo[2] = __float2bfloat16_rn(v.z - __bfloat162float(hi[2]));
                hi[3] = __float2bfloat16_rn(v.w); lo[3] = __float2bfloat16_rn(v.w - __bfloat162float(hi[3]));
                ((uint2*)dsthi)[i] = *(uint2*)hi;
                ((uint2*)dstlo)[i] = *(uint2*)lo;
            }
        } else {
            uint2 z = make_uint2(0, 0);
#pragma unroll
            for (int i = 0; i < 8; i++) { ((uint2*)dsthi)[i] = z; ((uint2*)dstlo)[i] = z; }
        }
    }
    // ---- W tiles (128 x 128 hi/lo, [n][k]): 4 threads/row ----
    {
        const __nv_bfloat16* w_hi_g = g_wThi + (size_t)mode * DIM * DIM;
        const __nv_bfloat16* w_lo_g = g_wTlo + (size_t)mode * DIM * DIM;
        int r = t >> 2;
        int c0 = (t & 3) * 32;
        const uint4* wh = (const uint4*)(w_hi_g + (size_t)r * DIM + c0);
        const uint4* wl = (const uint4*)(w_lo_g + (size_t)r * DIM + c0);
        char* dwh = smem + QK_WHI + r * ROW_BYTES + c0 * 2;
        char* dwl = smem + QK_WLO + r * ROW_BYTES + c0 * 2;
#pragma unroll
        for (int i = 0; i < 4; i++) {
            ((uint4*)dwh)[i] = wh[i];
            ((uint4*)dwl)[i] = wl[i];
        }
    }
    __syncthreads();

    int warp = t >> 5;                 // 0..15
    int lane = t & 31;
    int g  = lane >> 2;
    int tg = lane & 3;
    int m_base = (warp >> 2) * 32;     // 0,32,64,96
    int n_base = (warp & 3) * 32;      // 0,32,64,96

    unsigned a_off = (unsigned)((m_base + (lane & 15)) * ROW_BYTES + ((lane >> 4) << 3) * 2);
    unsigned b_off = (unsigned)((n_base + (lane & 7) + ((lane >> 4) << 3)) * ROW_BYTES
                                + (((lane >> 3) & 1) << 3) * 2);

    float acc[2][4][4];
#pragma unroll
    for (int mi = 0; mi < 2; mi++)
#pragma unroll
        for (int ni = 0; ni < 4; ni++)
#pragma unroll
            for (int j = 0; j < 4; j++) acc[mi][ni][j] = 0.0f;

    unsigned Af[2][16], Bf[2][16];
    qkv_load_frags(Af[0], Bf[0], smem_u, a_off, b_off, 0);
#pragma unroll
    for (int k0 = 0; k0 < 8; k0++) {
        int cur = k0 & 1;
        if (k0 < 7)
            qkv_load_frags(Af[cur ^ 1], Bf[cur ^ 1], smem_u, a_off, b_off, (unsigned)((k0 + 1) * 32));
        qkv_frag_mma(acc, Af[cur], Bf[cur]);
    }

    // ---- epilogue ----
#pragma unroll
    for (int mi = 0; mi < 2; mi++) {
#pragma unroll
        for (int ni = 0; ni < 4; ni++) {
            int c = n_base + ni * 8 + 2 * tg;
            int r0 = row0 + m_base + mi * 16 + g;
            int r1 = r0 + 8;
            if (r0 < NNODES)
                *(float2*)(outp + (size_t)r0 * DIM + c) = make_float2(acc[mi][ni][0], acc[mi][ni][1]);
            if (r1 < NNODES)
                *(float2*)(outp + (size_t)r1 * DIM + c) = make_float2(acc[mi][ni][2], acc[mi][ni][3]);
        }
    }
}

// ================= output GEMM: 64-row tiles, (256,2) =================
#define A_HI_OFF 0
#define A_LO_OFF 17408
#define W_HI_OFF 34816
#define W_LO_OFF 69632
#define SMEM_TOTAL 104448

__device__ __forceinline__ void load_frags(unsigned* A, unsigned* B, unsigned smem_u,
                                           unsigned a_off, unsigned b_off, unsigned kb) {
    ldsm_x4(A[0], A[1], A[2], A[3],     smem_u + A_HI_OFF + a_off + kb);
    ldsm_x4(A[4], A[5], A[6], A[7],     smem_u + A_HI_OFF + a_off + 16 * ROW_BYTES + kb);
    ldsm_x4(A[8], A[9], A[10], A[11],   smem_u + A_LO_OFF + a_off + kb);
    ldsm_x4(A[12], A[13], A[14], A[15], smem_u + A_LO_OFF + a_off + 16 * ROW_BYTES + kb);
    ldsm_x4(B[0], B[1], B[2], B[3],     smem_u + W_HI_OFF + b_off + kb);
    ldsm_x4(B[4], B[5], B[6], B[7],     smem_u + W_HI_OFF + b_off + 16 * ROW_BYTES + kb);
    ldsm_x4(B[8], B[9], B[10], B[11],   smem_u + W_LO_OFF + b_off + kb);
    ldsm_x4(B[12], B[13], B[14], B[15], smem_u + W_LO_OFF + b_off + 16 * ROW_BYTES + kb);
}

__device__ __forceinline__ void frag_mma(float acc[2][4][4], const unsigned* A, const unsigned* B) {
#pragma unroll
    for (int ni = 0; ni < 4; ni++)
#pragma unroll
        for (int mi = 0; mi < 2; mi++)
            mma_bf16(acc[mi][ni], A + mi * 4, B[ni * 2], B[ni * 2 + 1]);
#pragma unroll
    for (int ni = 0; ni < 4; ni++)
#pragma unroll
        for (int mi = 0; mi < 2; mi++)
            mma_bf16(acc[mi][ni], A + mi * 4, B[8 + ni * 2], B[8 + ni * 2 + 1]);
#pragma unroll
    for (int ni = 0; ni < 4; ni++)
#pragma unroll
        for (int mi = 0; mi < 2; mi++)
            mma_bf16(acc[mi][ni], A + 8 + mi * 4, B[ni * 2], B[ni * 2 + 1]);
}

__global__ __launch_bounds__(256, 2) void k_mma_out(const float* __restrict__ x,
                                                    const float* __restrict__ bout,
                                                    float* __restrict__ dout) {
    extern __shared__ char smem[];
    unsigned smem_u = (unsigned)__cvta_generic_to_shared(smem);
    int t = threadIdx.x;
    int row0 = blockIdx.x * 64;

    {
        int r = t >> 2;
        int c0 = (t & 3) * 32;
        int gr = row0 + r;
        char* dsthi = smem + A_HI_OFF + r * ROW_BYTES + c0 * 2;
        char* dstlo = smem + A_LO_OFF + r * ROW_BYTES + c0 * 2;
        if (gr < NNODES) {
            const uint4* sh = (const uint4*)(g_ahi + (size_t)gr * DIM + c0);
            const uint4* sl = (const uint4*)(g_alo + (size_t)gr * DIM + c0);
#pragma unroll
            for (int i = 0; i < 4; i++) {
                ((uint4*)dsthi)[i] = sh[i];
                ((uint4*)dstlo)[i] = sl[i];
            }
        } else {
            uint4 z = make_uint4(0, 0, 0, 0);
#pragma unroll
            for (int i = 0; i < 4; i++) { ((uint4*)dsthi)[i] = z; ((uint4*)dstlo)[i] = z; }
        }
    }
    {
        const __nv_bfloat16* w_hi_g = g_wThi + (size_t)3 * DIM * DIM;
        const __nv_bfloat16* w_lo_g = g_wTlo + (size_t)3 * DIM * DIM;
        int r = t >> 1;
        int half = (t & 1) * 64;
        const uint4* wh = (const uint4*)(w_hi_g + (size_t)r * DIM + half);
        const uint4* wl = (const uint4*)(w_lo_g + (size_t)r * DIM + half);
        char* dwh = smem + W_HI_OFF + r * ROW_BYTES + half * 2;
        char* dwl = smem + W_LO_OFF + r * ROW_BYTES + half * 2;
#pragma unroll
        for (int i = 0; i < 8; i++) {
            ((uint4*)dwh)[i] = wh[i];
            ((uint4*)dwl)[i] = wl[i];
        }
    }
    __syncthreads();

    int warp = t >> 5;
    int lane = t & 31;
    int g  = lane >> 2;
    int tg = lane & 3;
    int m_base = (warp >> 2) * 32;
    int n_base = (warp & 3) * 32;

    unsigned a_off = (unsigned)((m_base + (lane & 15)) * ROW_BYTES + ((lane >> 4) << 3) * 2);
    unsigned b_off = (unsigned)((n_base + (lane & 7) + ((lane >> 4) << 3)) * ROW_BYTES
                                + (((lane >> 3) & 1) << 3) * 2);

    float acc[2][4][4];
#pragma unroll
    for (int mi = 0; mi < 2; mi++)
#pragma unroll
        for (int ni = 0; ni < 4; ni++)
#pragma unroll
            for (int j = 0; j < 4; j++) acc[mi][ni][j] = 0.0f;

    unsigned Af[2][16], Bf[2][16];
    load_frags(Af[0], Bf[0], smem_u, a_off, b_off, 0);
#pragma unroll
    for (int k0 = 0; k0 < 8; k0++) {
        int cur = k0 & 1;
        if (k0 < 7)
            load_frags(Af[cur ^ 1], Bf[cur ^ 1], smem_u, a_off, b_off, (unsigned)((k0 + 1) * 32));
        frag_mma(acc, Af[cur], Bf[cur]);
    }

#pragma unroll
    for (int mi = 0; mi < 2; mi++) {
#pragma unroll
        for (int ni = 0; ni < 4; ni++) {
            int c = n_base + ni * 8 + 2 * tg;
            int r0 = row0 + m_base + mi * 16 + g;
            int r1 = r0 + 8;
            float2 b = *(const float2*)(bout + c);
            if (r0 < NNODES) {
                float2 xr = *(const float2*)(x + (size_t)r0 * DIM + c);
                float2 v0;
                v0.x = fmaxf(acc[mi][ni][0] + b.x, 0.0f) + xr.x;
                v0.y = fmaxf(acc[mi][ni][1] + b.y, 0.0f) + xr.y;
                *(float2*)(dout + (size_t)r0 * DIM + c) = v0;
            }
            if (r1 < NNODES) {
                float2 xr = *(const float2*)(x + (size_t)r1 * DIM + c);
                float2 v1;
                v1.x = fmaxf(acc[mi][ni][2] + b.x, 0.0f) + xr.x;
                v1.y = fmaxf(acc[mi][ni][3] + b.y, 0.0f) + xr.y;
                *(float2*)(dout + (size_t)r1 * DIM + c) = v1;
            }
        }
    }
}

// ---------------- launch ----------------
extern "C" void kernel_launch(void* const* d_in, const int* in_sizes, int n_in,
                              void* d_out, int out_size) {
    const float* x      = (const float*)d_in[0];
    const int* ei       = (const int*)d_in[1];
    const float* Wt     = (const float*)d_in[2];
    const float* Ws     = (const float*)d_in[3];
    const float* Wc     = (const float*)d_in[4];
    const float* Wout   = (const float*)d_in[5];
    const float* bout   = (const float*)d_in[6];
    float* out          = (float*)d_out;

    static bool configured = false;
    if (!configured) {
        cudaFuncSetAttribute(k_mma_qkv, cudaFuncAttributeMaxDynamicSharedMemorySize, QK_SMEM);
        cudaFuncSetAttribute(k_mma_out, cudaFuncAttributeMaxDynamicSharedMemorySize, SMEM_TOTAL);
        configured = true;
    }

    // 5 launches -> profile slot 3 = k_fused
    k_prep<<<256, 256>>>(Wt, Ws, Wc, Wout);                          // 0
    k_fill<<<(NEDGES + 255) / 256, 256>>>(ei);                       // 1
    dim3 gq((NNODES + 127) / 128, 3);
    k_mma_qkv<<<gq, 512, QK_SMEM>>>(x);                              // 2
    k_fused<<<(NNODES * 32 + 255) / 256, 256>>>();                   // 3 <- profiled
    k_mma_out<<<(NNODES + 63) / 64, 256, SMEM_TOTAL>>>(x, bout, out); // 4
}

// round 14
// speedup vs baseline: 1.0743x; 1.0408x over previous
#include <cuda_runtime.h>
#include <cuda_bf16.h>

#define NNODES 50000
#define NEDGES 800000
#define DIM 128
#define NH 4
#define MAXDEG 128

// ---------------- scratch (device globals: no allocs allowed) ----------------
__device__ __align__(16) float g_q[NNODES * DIM];
__device__ __align__(16) float g_k[NNODES * DIM];
__device__ __align__(16) float g_v[NNODES * DIM];

__device__ int g_deg[NNODES];
__device__ int g_bucket[NNODES * MAXDEG];

__device__ __align__(16) __nv_bfloat16 g_ahi[NNODES * DIM];
__device__ __align__(16) __nv_bfloat16 g_alo[NNODES * DIM];
__device__ __align__(16) __nv_bfloat16 g_wThi[4 * DIM * DIM];
__device__ __align__(16) __nv_bfloat16 g_wTlo[4 * DIM * DIM];

// ---------------- prep: zero degrees + split/transpose weights ----------------
__global__ __launch_bounds__(256) void k_prep(const float* __restrict__ Wt,
                                              const float* __restrict__ Ws,
                                              const float* __restrict__ Wc,
                                              const float* __restrict__ Wout) {
    int t = blockIdx.x * blockDim.x + threadIdx.x;
    if (t < NNODES) g_deg[t] = 0;
    if (t < 4 * DIM * DIM) {
        int w = t >> 14;
        int idx = t & 16383;
        int k = idx >> 7;
        int n = idx & 127;
        const float* W = (w == 0) ? Wt : (w == 1) ? Ws : (w == 2) ? Wc : Wout;
        float v = W[k * DIM + n];
        __nv_bfloat16 h = __float2bfloat16_rn(v);
        g_wThi[(size_t)w * DIM * DIM + n * DIM + k] = h;
        g_wTlo[(size_t)w * DIM * DIM + n * DIM + k] = __float2bfloat16_rn(v - __bfloat162float(h));
    }
}

// ---------------- fused scores + softmax + aggregation (one warp / dst) ----------------
// 4-edge unroll; minBlocksPerMP=5 caps regs ~51 -> 5 CTAs/SM for latency hiding
__global__ __launch_bounds__(256, 5) void k_fused() {
    int n = (blockIdx.x * blockDim.x + threadIdx.x) >> 5;
    if (n >= NNODES) return;
    int l = threadIdx.x & 31;
    int start = n * MAXDEG;
    int deg = g_deg[n];

    float4 qv = *(const float4*)(g_q + (size_t)n * DIM + (l << 2));
    float denom = 0.0f;
    float4 vacc = make_float4(0.f, 0.f, 0.f, 0.f);

    int j = 0;
    for (; j + 3 < deg; j += 4) {
        int s0 = g_bucket[start + j];
        int s1 = g_bucket[start + j + 1];
        int s2 = g_bucket[start + j + 2];
        int s3 = g_bucket[start + j + 3];
        float4 k0 = *(const float4*)(g_k + (size_t)s0 * DIM + (l << 2));
        float4 k1 = *(const float4*)(g_k + (size_t)s1 * DIM + (l << 2));
        float4 k2 = *(const float4*)(g_k + (size_t)s2 * DIM + (l << 2));
        float4 k3 = *(const float4*)(g_k + (size_t)s3 * DIM + (l << 2));
        float4 v0 = *(const float4*)(g_v + (size_t)s0 * DIM + (l << 2));
        float4 v1 = *(const float4*)(g_v + (size_t)s1 * DIM + (l << 2));
        float4 v2 = *(const float4*)(g_v + (size_t)s2 * DIM + (l << 2));
        float4 v3 = *(const float4*)(g_v + (size_t)s3 * DIM + (l << 2));
        float p0 = qv.x * k0.x + qv.y * k0.y + qv.z * k0.z + qv.w * k0.w;
        float p1 = qv.x * k1.x + qv.y * k1.y + qv.z * k1.z + qv.w * k1.w;
        float p2 = qv.x * k2.x + qv.y * k2.y + qv.z * k2.z + qv.w * k2.w;
        float p3 = qv.x * k3.x + qv.y * k3.y + qv.z * k3.z + qv.w * k3.w;
        p0 += __shfl_xor_sync(0xffffffffu, p0, 1);
        p1 += __shfl_xor_sync(0xffffffffu, p1, 1);
        p2 += __shfl_xor_sync(0xffffffffu, p2, 1);
        p3 += __shfl_xor_sync(0xffffffffu, p3, 1);
        p0 += __shfl_xor_sync(0xffffffffu, p0, 2);
        p1 += __shfl_xor_sync(0xffffffffu, p1, 2);
        p2 += __shfl_xor_sync(0xffffffffu, p2, 2);
        p3 += __shfl_xor_sync(0xffffffffu, p3, 2);
        p0 += __shfl_xor_sync(0xffffffffu, p0, 4);
        p1 += __shfl_xor_sync(0xffffffffu, p1, 4);
        p2 += __shfl_xor_sync(0xffffffffu, p2, 4);
        p3 += __shfl_xor_sync(0xffffffffu, p3, 4);
        float e0 = __expf(p0);
        float e1 = __expf(p1);
        float e2 = __expf(p2);
        float e3 = __expf(p3);
        denom += (e0 + e1) + (e2 + e3);
        vacc.x = fmaf(e0, v0.x, fmaf(e1, v1.x, fmaf(e2, v2.x, fmaf(e3, v3.x, vacc.x))));
        vacc.y = fmaf(e0, v0.y, fmaf(e1, v1.y, fmaf(e2, v2.y, fmaf(e3, v3.y, vacc.y))));
        vacc.z = fmaf(e0, v0.z, fmaf(e1, v1.z, fmaf(e2, v2.z, fmaf(e3, v3.z, vacc.z))));
        vacc.w = fmaf(e0, v0.w, fmaf(e1, v1.w, fmaf(e2, v2.w, fmaf(e3, v3.w, vacc.w))));
    }
    for (; j < deg; j++) {
        int s0 = g_bucket[start + j];
        float4 k0 = *(const float4*)(g_k + (size_t)s0 * DIM + (l << 2));
        float4 v0 = *(const float4*)(g_v + (size_t)s0 * DIM + (l << 2));
        float p0 = qv.x * k0.x + qv.y * k0.y + qv.z * k0.z + qv.w * k0.w;
        p0 += __shfl_xor_sync(0xffffffffu, p0, 1);
        p0 += __shfl_xor_sync(0xffffffffu, p0, 2);
        p0 += __shfl_xor_sync(0xffffffffu, p0, 4);
        float e0 = __expf(p0);
        denom += e0;
        vacc.x = fmaf(e0, v0.x, vacc.x);
        vacc.y = fmaf(e0, v0.y, vacc.y);
        vacc.z = fmaf(e0, v0.z, vacc.z);
        vacc.w = fmaf(e0, v0.w, vacc.w);
    }
    float inv = (deg > 0) ? __fdividef(1.0f, denom) : 0.0f;
    float o[4] = {vacc.x * inv, vacc.y * inv, vacc.z * inv, vacc.w * inv};
    __nv_bfloat16 hi[4], lo[4];
#pragma unroll
    for (int i = 0; i < 4; i++) {
        hi[i] = __float2bfloat16_rn(o[i]);
        lo[i] = __float2bfloat16_rn(o[i] - __bfloat162float(hi[i]));
    }
    *(uint2*)(g_ahi + (size_t)n * DIM + (l << 2)) = *(uint2*)hi;
    *(uint2*)(g_alo + (size_t)n * DIM + (l << 2)) = *(uint2*)lo;
}

// ---------------- split-bf16 mma.sync GEMM bits ----------------
#define SMEM_STRIDE 136
#define ROW_BYTES   (SMEM_STRIDE * 2)   // 272 -> LDSM conflict-free (bank step 4)

__device__ __forceinline__ void mma_bf16(float* c, const unsigned* a, unsigned b0, unsigned b1) {
    asm volatile(
        "mma.sync.aligned.m16n8k16.row.col.f32.bf16.bf16.f32 "
        "{%0,%1,%2,%3}, {%4,%5,%6,%7}, {%8,%9}, {%0,%1,%2,%3};"
        : "+f"(c[0]), "+f"(c[1]), "+f"(c[2]), "+f"(c[3])
        : "r"(a[0]), "r"(a[1]), "r"(a[2]), "r"(a[3]), "r"(b0), "r"(b1));
}

__device__ __forceinline__ void ldsm_x4(unsigned& r0, unsigned& r1, unsigned& r2, unsigned& r3,
                                        unsigned addr) {
    asm volatile("ldmatrix.sync.aligned.m8n8.x4.shared.b16 {%0,%1,%2,%3}, [%4];"
                 : "=r"(r0), "=r"(r1), "=r"(r2), "=r"(r3) : "r"(addr));
}

// ================= QKV GEMM: 128-row CTA tile, 512 threads, warp tile 32x32 =================
// blockIdx.y==3 blocks perform the edge bucket fill (overlapped with GEMM work)
#define QK_AHI 0
#define QK_ALO 34816
#define QK_WHI 69632
#define QK_WLO 104448
#define QK_SMEM 139264

__device__ __forceinline__ void qkv_load_frags(unsigned* A, unsigned* B, unsigned smem_u,
                                               unsigned a_off, unsigned b_off, unsigned kb) {
    ldsm_x4(A[0], A[1], A[2], A[3],     smem_u + QK_AHI + a_off + kb);
    ldsm_x4(A[4], A[5], A[6], A[7],     smem_u + QK_AHI + a_off + 16 * ROW_BYTES + kb);
    ldsm_x4(A[8], A[9], A[10], A[11],   smem_u + QK_ALO + a_off + kb);
    ldsm_x4(A[12], A[13], A[14], A[15], smem_u + QK_ALO + a_off + 16 * ROW_BYTES + kb);
    ldsm_x4(B[0], B[1], B[2], B[3],     smem_u + QK_WHI + b_off + kb);
    ldsm_x4(B[4], B[5], B[6], B[7],     smem_u + QK_WHI + b_off + 16 * ROW_BYTES + kb);
    ldsm_x4(B[8], B[9], B[10], B[11],   smem_u + QK_WLO + b_off + kb);
    ldsm_x4(B[12], B[13], B[14], B[15], smem_u + QK_WLO + b_off + 16 * ROW_BYTES + kb);
}

__device__ __forceinline__ void qkv_frag_mma(float acc[2][4][4], const unsigned* A, const unsigned* B) {
#pragma unroll
    for (int ni = 0; ni < 4; ni++)
#pragma unroll
        for (int mi = 0; mi < 2; mi++)
            mma_bf16(acc[mi][ni], A + mi * 4, B[ni * 2], B[ni * 2 + 1]);            // hi*hi
#pragma unroll
    for (int ni = 0; ni < 4; ni++)
#pragma unroll
        for (int mi = 0; mi < 2; mi++)
            mma_bf16(acc[mi][ni], A + mi * 4, B[8 + ni * 2], B[8 + ni * 2 + 1]);    // hi*lo
#pragma unroll
    for (int ni = 0; ni < 4; ni++)
#pragma unroll
        for (int mi = 0; mi < 2; mi++)
            mma_bf16(acc[mi][ni], A + 8 + mi * 4, B[ni * 2], B[ni * 2 + 1]);        // lo*hi
}

__global__ __launch_bounds__(512, 1) void k_mma_qkv(const float* __restrict__ x,
                                                    const int* __restrict__ ei) {
    // ---- fill path: blockIdx.y == 3 (no smem use) ----
    if (blockIdx.y == 3) {
        int base = (blockIdx.x * 512 + threadIdx.x) * 4;
#pragma unroll
        for (int i = 0; i < 4; i++) {
            int e = base + i;
            if (e < NEDGES) {
                int src = ei[e];
                int dst = ei[NEDGES + e];
                int pos = atomicAdd(&g_deg[dst], 1);
                g_bucket[dst * MAXDEG + pos] = src;
            }
        }
        return;
    }

    extern __shared__ char smem[];
    unsigned smem_u = (unsigned)__cvta_generic_to_shared(smem);
    int t = threadIdx.x;
    int mode = blockIdx.y;
    int row0 = blockIdx.x * 128;
    float* outp = (mode == 0) ? g_q : (mode == 1) ? g_k : g_v;

    // ---- load + split A tile (128 x 128): 4 threads/row ----
    {
        int r = t >> 2;
        int c0 = (t & 3) * 32;
        int gr = row0 + r;
        char* dsthi = smem + QK_AHI + r * ROW_BYTES + c0 * 2;
        char* dstlo = smem + QK_ALO + r * ROW_BYTES + c0 * 2;
        if (gr < NNODES) {
            const float4* srcp = (const float4*)(x + (size_t)gr * DIM + c0);
#pragma unroll
            for (int i = 0; i < 8; i++) {
                float4 v = srcp[i];
                __nv_bfloat16 hi[4], lo[4];
                hi[0] = __float2bfloat16_rn(v.x); lo[0] = __float2bfloat16_rn(v.x - __bfloat162float(hi[0]));
                hi[1] = __float2bfloat16_rn(v.y); lo[1] = __float2bfloat16_rn(v.y - __bfloat162float(hi[1]));
                hi[2] = __float2bfloat16_rn(v.z); lo[2] = __float2bfloat16_rn(v.z - __bfloat162float(hi[2]));
                hi[3] = __float2bfloat16_rn(v.w); lo[3] = __float2bfloat16_rn(v.w - __bfloat162float(hi[3]));
                ((uint2*)dsthi)[i] = *(uint2*)hi;
                ((uint2*)dstlo)[i] = *(uint2*)lo;
            }
        } else {
            uint2 z = make_uint2(0, 0);
#pragma unroll
            for (int i = 0; i < 8; i++) { ((uint2*)dsthi)[i] = z; ((uint2*)dstlo)[i] = z; }
        }
    }
    // ---- W tiles (128 x 128 hi/lo, [n][k]): 4 threads/row ----
    {
        const __nv_bfloat16* w_hi_g = g_wThi + (size_t)mode * DIM * DIM;
        const __nv_bfloat16* w_lo_g = g_wTlo + (size_t)mode * DIM * DIM;
        int r = t >> 2;
        int c0 = (t & 3) * 32;
        const uint4* wh = (const uint4*)(w_hi_g + (size_t)r * DIM + c0);
        const uint4* wl = (const uint4*)(w_lo_g + (size_t)r * DIM + c0);
        char* dwh = smem + QK_WHI + r * ROW_BYTES + c0 * 2;
        char* dwl = smem + QK_WLO + r * ROW_BYTES + c0 * 2;
#pragma unroll
        for (int i = 0; i < 4; i++) {
            ((uint4*)dwh)[i] = wh[i];
            ((uint4*)dwl)[i] = wl[i];
        }
    }
    __syncthreads();

    int warp = t >> 5;                 // 0..15
    int lane = t & 31;
    int g  = lane >> 2;
    int tg = lane & 3;
    int m_base = (warp >> 2) * 32;     // 0,32,64,96
    int n_base = (warp & 3) * 32;      // 0,32,64,96

    unsigned a_off = (unsigned)((m_base + (lane & 15)) * ROW_BYTES + ((lane >> 4) << 3) * 2);
    unsigned b_off = (unsigned)((n_base + (lane & 7) + ((lane >> 4) << 3)) * ROW_BYTES
                                + (((lane >> 3) & 1) << 3) * 2);

    float acc[2][4][4];
#pragma unroll
    for (int mi = 0; mi < 2; mi++)
#pragma unroll
        for (int ni = 0; ni < 4; ni++)
#pragma unroll
            for (int j = 0; j < 4; j++) acc[mi][ni][j] = 0.0f;

    unsigned Af[2][16], Bf[2][16];
    qkv_load_frags(Af[0], Bf[0], smem_u, a_off, b_off, 0);
#pragma unroll
    for (int k0 = 0; k0 < 8; k0++) {
        int cur = k0 & 1;
        if (k0 < 7)
            qkv_load_frags(Af[cur ^ 1], Bf[cur ^ 1], smem_u, a_off, b_off, (unsigned)((k0 + 1) * 32));
        qkv_frag_mma(acc, Af[cur], Bf[cur]);
    }

    // ---- epilogue ----
#pragma unroll
    for (int mi = 0; mi < 2; mi++) {
#pragma unroll
        for (int ni = 0; ni < 4; ni++) {
            int c = n_base + ni * 8 + 2 * tg;
            int r0 = row0 + m_base + mi * 16 + g;
            int r1 = r0 + 8;
            if (r0 < NNODES)
                *(float2*)(outp + (size_t)r0 * DIM + c) = make_float2(acc[mi][ni][0], acc[mi][ni][1]);
            if (r1 < NNODES)
                *(float2*)(outp + (size_t)r1 * DIM + c) = make_float2(acc[mi][ni][2], acc[mi][ni][3]);
        }
    }
}

// ================= output GEMM: 64-row tiles, (256,2) =================
#define A_HI_OFF 0
#define A_LO_OFF 17408
#define W_HI_OFF 34816
#define W_LO_OFF 69632
#define SMEM_TOTAL 104448

__device__ __forceinline__ void load_frags(unsigned* A, unsigned* B, unsigned smem_u,
                                           unsigned a_off, unsigned b_off, unsigned kb) {
    ldsm_x4(A[0], A[1], A[2], A[3],     smem_u + A_HI_OFF + a_off + kb);
    ldsm_x4(A[4], A[5], A[6], A[7],     smem_u + A_HI_OFF + a_off + 16 * ROW_BYTES + kb);
    ldsm_x4(A[8], A[9], A[10], A[11],   smem_u + A_LO_OFF + a_off + kb);
    ldsm_x4(A[12], A[13], A[14], A[15], smem_u + A_LO_OFF + a_off + 16 * ROW_BYTES + kb);
    ldsm_x4(B[0], B[1], B[2], B[3],     smem_u + W_HI_OFF + b_off + kb);
    ldsm_x4(B[4], B[5], B[6], B[7],     smem_u + W_HI_OFF + b_off + 16 * ROW_BYTES + kb);
    ldsm_x4(B[8], B[9], B[10], B[11],   smem_u + W_LO_OFF + b_off + kb);
    ldsm_x4(B[12], B[13], B[14], B[15], smem_u + W_LO_OFF + b_off + 16 * ROW_BYTES + kb);
}

__device__ __forceinline__ void frag_mma(float acc[2][4][4], const unsigned* A, const unsigned* B) {
#pragma unroll
    for (int ni = 0; ni < 4; ni++)
#pragma unroll
        for (int mi = 0; mi < 2; mi++)
            mma_bf16(acc[mi][ni], A + mi * 4, B[ni * 2], B[ni * 2 + 1]);
#pragma unroll
    for (int ni = 0; ni < 4; ni++)
#pragma unroll
        for (int mi = 0; mi < 2; mi++)
            mma_bf16(acc[mi][ni], A + mi * 4, B[8 + ni * 2], B[8 + ni * 2 + 1]);
#pragma unroll
    for (int ni = 0; ni < 4; ni++)
#pragma unroll
        for (int mi = 0; mi < 2; mi++)
            mma_bf16(acc[mi][ni], A + 8 + mi * 4, B[ni * 2], B[ni * 2 + 1]);
}

__global__ __launch_bounds__(256, 2) void k_mma_out(const float* __restrict__ x,
                                                    const float* __restrict__ bout,
                                                    float* __restrict__ dout) {
    extern __shared__ char smem[];
    unsigned smem_u = (unsigned)__cvta_generic_to_shared(smem);
    int t = threadIdx.x;
    int row0 = blockIdx.x * 64;

    {
        int r = t >> 2;
        int c0 = (t & 3) * 32;
        int gr = row0 + r;
        char* dsthi = smem + A_HI_OFF + r * ROW_BYTES + c0 * 2;
        char* dstlo = smem + A_LO_OFF + r * ROW_BYTES + c0 * 2;
        if (gr < NNODES) {
            const uint4* sh = (const uint4*)(g_ahi + (size_t)gr * DIM + c0);
            const uint4* sl = (const uint4*)(g_alo + (size_t)gr * DIM + c0);
#pragma unroll
            for (int i = 0; i < 4; i++) {
                ((uint4*)dsthi)[i] = sh[i];
                ((uint4*)dstlo)[i] = sl[i];
            }
        } else {
            uint4 z = make_uint4(0, 0, 0, 0);
#pragma unroll
            for (int i = 0; i < 4; i++) { ((uint4*)dsthi)[i] = z; ((uint4*)dstlo)[i] = z; }
        }
    }
    {
        const __nv_bfloat16* w_hi_g = g_wThi + (size_t)3 * DIM * DIM;
        const __nv_bfloat16* w_lo_g = g_wTlo + (size_t)3 * DIM * DIM;
        int r = t >> 1;
        int half = (t & 1) * 64;
        const uint4* wh = (const uint4*)(w_hi_g + (size_t)r * DIM + half);
        const uint4* wl = (const uint4*)(w_lo_g + (size_t)r * DIM + half);
        char* dwh = smem + W_HI_OFF + r * ROW_BYTES + half * 2;
        char* dwl = smem + W_LO_OFF + r * ROW_BYTES + half * 2;
#pragma unroll
        for (int i = 0; i < 8; i++) {
            ((uint4*)dwh)[i] = wh[i];
            ((uint4*)dwl)[i] = wl[i];
        }
    }
    __syncthreads();

    int warp = t >> 5;
    int lane = t & 31;
    int g  = lane >> 2;
    int tg = lane & 3;
    int m_base = (warp >> 2) * 32;
    int n_base = (warp & 3) * 32;

    unsigned a_off = (unsigned)((m_base + (lane & 15)) * ROW_BYTES + ((lane >> 4) << 3) * 2);
    unsigned b_off = (unsigned)((n_base + (lane & 7) + ((lane >> 4) << 3)) * ROW_BYTES
                                + (((lane >> 3) & 1) << 3) * 2);

    float acc[2][4][4];
#pragma unroll
    for (int mi = 0; mi < 2; mi++)
#pragma unroll
        for (int ni = 0; ni < 4; ni++)
#pragma unroll
            for (int j = 0; j < 4; j++) acc[mi][ni][j] = 0.0f;

    unsigned Af[2][16], Bf[2][16];
    load_frags(Af[0], Bf[0], smem_u, a_off, b_off, 0);
#pragma unroll
    for (int k0 = 0; k0 < 8; k0++) {
        int cur = k0 & 1;
        if (k0 < 7)
            load_frags(Af[cur ^ 1], Bf[cur ^ 1], smem_u, a_off, b_off, (unsigned)((k0 + 1) * 32));
        frag_mma(acc, Af[cur], Bf[cur]);
    }

#pragma unroll
    for (int mi = 0; mi < 2; mi++) {
#pragma unroll
        for (int ni = 0; ni < 4; ni++) {
            int c = n_base + ni * 8 + 2 * tg;
            int r0 = row0 + m_base + mi * 16 + g;
            int r1 = r0 + 8;
            float2 b = *(const float2*)(bout + c);
            if (r0 < NNODES) {
                float2 xr = *(const float2*)(x + (size_t)r0 * DIM + c);
                float2 v0;
                v0.x = fmaxf(acc[mi][ni][0] + b.x, 0.0f) + xr.x;
                v0.y = fmaxf(acc[mi][ni][1] + b.y, 0.0f) + xr.y;
                *(float2*)(dout + (size_t)r0 * DIM + c) = v0;
            }
            if (r1 < NNODES) {
                float2 xr = *(const float2*)(x + (size_t)r1 * DIM + c);
                float2 v1;
                v1.x = fmaxf(acc[mi][ni][2] + b.x, 0.0f) + xr.x;
                v1.y = fmaxf(acc[mi][ni][3] + b.y, 0.0f) + xr.y;
                *(float2*)(dout + (size_t)r1 * DIM + c) = v1;
            }
        }
    }
}

// ---------------- launch ----------------
extern "C" void kernel_launch(void* const* d_in, const int* in_sizes, int n_in,
                              void* d_out, int out_size) {
    const float* x      = (const float*)d_in[0];
    const int* ei       = (const int*)d_in[1];
    const float* Wt     = (const float*)d_in[2];
    const float* Ws     = (const float*)d_in[3];
    const float* Wc     = (const float*)d_in[4];
    const float* Wout   = (const float*)d_in[5];
    const float* bout   = (const float*)d_in[6];
    float* out          = (float*)d_out;

    static bool configured = false;
    if (!configured) {
        cudaFuncSetAttribute(k_mma_qkv, cudaFuncAttributeMaxDynamicSharedMemorySize, QK_SMEM);
        cudaFuncSetAttribute(k_mma_out, cudaFuncAttributeMaxDynamicSharedMemorySize, SMEM_TOTAL);
        configured = true;
    }

    // 4 launches -> profile slot 3 = k_mma_out
    k_prep<<<256, 256>>>(Wt, Ws, Wc, Wout);                           // 0
    dim3 gq((NNODES + 127) / 128, 4);   // y==3 -> bucket fill (391*512*4 >= NEDGES)
    k_mma_qkv<<<gq, 512, QK_SMEM>>>(x, ei);                           // 1
    k_fused<<<(NNODES * 32 + 255) / 256, 256>>>();                    // 2
    k_mma_out<<<(NNODES + 63) / 64, 256, SMEM_TOTAL>>>(x, bout, out); // 3 <- profiled
}

// round 15
// speedup vs baseline: 1.1322x; 1.0539x over previous
#include <cuda_runtime.h>
#include <cuda_bf16.h>

#define NNODES 50000
#define NEDGES 800000
#define DIM 128
#define NH 4
#define MAXDEG 128

// ---------------- scratch (device globals: no allocs allowed) ----------------
__device__ __align__(16) float g_q[NNODES * DIM];
__device__ __align__(16) float g_k[NNODES * DIM];
__device__ __align__(16) float g_v[NNODES * DIM];

__device__ int g_deg[NNODES];
__device__ int g_bucket[NNODES * MAXDEG];

__device__ __align__(16) __nv_bfloat16 g_ahi[NNODES * DIM];
__device__ __align__(16) __nv_bfloat16 g_alo[NNODES * DIM];
__device__ __align__(16) __nv_bfloat16 g_wThi[4 * DIM * DIM];
__device__ __align__(16) __nv_bfloat16 g_wTlo[4 * DIM * DIM];

// ---------------- prep: zero degrees + split/transpose weights ----------------
__global__ __launch_bounds__(256) void k_prep(const float* __restrict__ Wt,
                                              const float* __restrict__ Ws,
                                              const float* __restrict__ Wc,
                                              const float* __restrict__ Wout) {
    int t = blockIdx.x * blockDim.x + threadIdx.x;
    if (t < NNODES) g_deg[t] = 0;
    if (t < 4 * DIM * DIM) {
        int w = t >> 14;
        int idx = t & 16383;
        int k = idx >> 7;
        int n = idx & 127;
        const float* W = (w == 0) ? Wt : (w == 1) ? Ws : (w == 2) ? Wc : Wout;
        float v = W[k * DIM + n];
        __nv_bfloat16 h = __float2bfloat16_rn(v);
        g_wThi[(size_t)w * DIM * DIM + n * DIM + k] = h;
        g_wTlo[(size_t)w * DIM * DIM + n * DIM + k] = __float2bfloat16_rn(v - __bfloat162float(h));
    }
}

// ---------------- fused scores + softmax + aggregation (one warp / dst) ----------------
__global__ __launch_bounds__(256, 5) void k_fused() {
    int n = (blockIdx.x * blockDim.x + threadIdx.x) >> 5;
    if (n >= NNODES) return;
    int l = threadIdx.x & 31;
    int start = n * MAXDEG;
    int deg = g_deg[n];

    float4 qv = *(const float4*)(g_q + (size_t)n * DIM + (l << 2));
    float denom = 0.0f;
    float4 vacc = make_float4(0.f, 0.f, 0.f, 0.f);

    int j = 0;
    for (; j + 3 < deg; j += 4) {
        int s0 = g_bucket[start + j];
        int s1 = g_bucket[start + j + 1];
        int s2 = g_bucket[start + j + 2];
        int s3 = g_bucket[start + j + 3];
        float4 k0 = *(const float4*)(g_k + (size_t)s0 * DIM + (l << 2));
        float4 k1 = *(const float4*)(g_k + (size_t)s1 * DIM + (l << 2));
        float4 k2 = *(const float4*)(g_k + (size_t)s2 * DIM + (l << 2));
        float4 k3 = *(const float4*)(g_k + (size_t)s3 * DIM + (l << 2));
        float4 v0 = *(const float4*)(g_v + (size_t)s0 * DIM + (l << 2));
        float4 v1 = *(const float4*)(g_v + (size_t)s1 * DIM + (l << 2));
        float4 v2 = *(const float4*)(g_v + (size_t)s2 * DIM + (l << 2));
        float4 v3 = *(const float4*)(g_v + (size_t)s3 * DIM + (l << 2));
        float p0 = qv.x * k0.x + qv.y * k0.y + qv.z * k0.z + qv.w * k0.w;
        float p1 = qv.x * k1.x + qv.y * k1.y + qv.z * k1.z + qv.w * k1.w;
        float p2 = qv.x * k2.x + qv.y * k2.y + qv.z * k2.z + qv.w * k2.w;
        float p3 = qv.x * k3.x + qv.y * k3.y + qv.z * k3.z + qv.w * k3.w;
        p0 += __shfl_xor_sync(0xffffffffu, p0, 1);
        p1 += __shfl_xor_sync(0xffffffffu, p1, 1);
        p2 += __shfl_xor_sync(0xffffffffu, p2, 1);
        p3 += __shfl_xor_sync(0xffffffffu, p3, 1);
        p0 += __shfl_xor_sync(0xffffffffu, p0, 2);
        p1 += __shfl_xor_sync(0xffffffffu, p1, 2);
        p2 += __shfl_xor_sync(0xffffffffu, p2, 2);
        p3 += __shfl_xor_sync(0xffffffffu, p3, 2);
        p0 += __shfl_xor_sync(0xffffffffu, p0, 4);
        p1 += __shfl_xor_sync(0xffffffffu, p1, 4);
        p2 += __shfl_xor_sync(0xffffffffu, p2, 4);
        p3 += __shfl_xor_sync(0xffffffffu, p3, 4);
        float e0 = __expf(p0);
        float e1 = __expf(p1);
        float e2 = __expf(p2);
        float e3 = __expf(p3);
        denom += (e0 + e1) + (e2 + e3);
        vacc.x = fmaf(e0, v0.x, fmaf(e1, v1.x, fmaf(e2, v2.x, fmaf(e3, v3.x, vacc.x))));
        vacc.y = fmaf(e0, v0.y, fmaf(e1, v1.y, fmaf(e2, v2.y, fmaf(e3, v3.y, vacc.y))));
        vacc.z = fmaf(e0, v0.z, fmaf(e1, v1.z, fmaf(e2, v2.z, fmaf(e3, v3.z, vacc.z))));
        vacc.w = fmaf(e0, v0.w, fmaf(e1, v1.w, fmaf(e2, v2.w, fmaf(e3, v3.w, vacc.w))));
    }
    for (; j < deg; j++) {
        int s0 = g_bucket[start + j];
        float4 k0 = *(const float4*)(g_k + (size_t)s0 * DIM + (l << 2));
        float4 v0 = *(const float4*)(g_v + (size_t)s0 * DIM + (l << 2));
        float p0 = qv.x * k0.x + qv.y * k0.y + qv.z * k0.z + qv.w * k0.w;
        p0 += __shfl_xor_sync(0xffffffffu, p0, 1);
        p0 += __shfl_xor_sync(0xffffffffu, p0, 2);
        p0 += __shfl_xor_sync(0xffffffffu, p0, 4);
        float e0 = __expf(p0);
        denom += e0;
        vacc.x = fmaf(e0, v0.x, vacc.x);
        vacc.y = fmaf(e0, v0.y, vacc.y);
        vacc.z = fmaf(e0, v0.z, vacc.z);
        vacc.w = fmaf(e0, v0.w, vacc.w);
    }
    float inv = (deg > 0) ? __fdividef(1.0f, denom) : 0.0f;
    float o[4] = {vacc.x * inv, vacc.y * inv, vacc.z * inv, vacc.w * inv};
    __nv_bfloat16 hi[4], lo[4];
#pragma unroll
    for (int i = 0; i < 4; i++) {
        hi[i] = __float2bfloat16_rn(o[i]);
        lo[i] = __float2bfloat16_rn(o[i] - __bfloat162float(hi[i]));
    }
    *(uint2*)(g_ahi + (size_t)n * DIM + (l << 2)) = *(uint2*)hi;
    *(uint2*)(g_alo + (size_t)n * DIM + (l << 2)) = *(uint2*)lo;
}

// ---------------- split-bf16 mma.sync GEMM bits ----------------
#define SMEM_STRIDE 136
#define ROW_BYTES   (SMEM_STRIDE * 2)   // 272 -> LDSM conflict-free (bank step 4)

__device__ __forceinline__ void mma_bf16(float* c, const unsigned* a, unsigned b0, unsigned b1) {
    asm volatile(
        "mma.sync.aligned.m16n8k16.row.col.f32.bf16.bf16.f32 "
        "{%0,%1,%2,%3}, {%4,%5,%6,%7}, {%8,%9}, {%0,%1,%2,%3};"
        : "+f"(c[0]), "+f"(c[1]), "+f"(c[2]), "+f"(c[3])
        : "r"(a[0]), "r"(a[1]), "r"(a[2]), "r"(a[3]), "r"(b0), "r"(b1));
}

__device__ __forceinline__ void ldsm_x4(unsigned& r0, unsigned& r1, unsigned& r2, unsigned& r3,
                                        unsigned addr) {
    asm volatile("ldmatrix.sync.aligned.m8n8.x4.shared.b16 {%0,%1,%2,%3}, [%4];"
                 : "=r"(r0), "=r"(r1), "=r"(r2), "=r"(r3) : "r"(addr));
}

// ================= shared GEMM config: 128-row CTA tile, 512 threads, warp 32x32 =================
#define QK_AHI 0
#define QK_ALO 34816
#define QK_WHI 69632
#define QK_WLO 104448
#define QK_SMEM 139264

__device__ __forceinline__ void qkv_load_frags(unsigned* A, unsigned* B, unsigned smem_u,
                                               unsigned a_off, unsigned b_off, unsigned kb) {
    ldsm_x4(A[0], A[1], A[2], A[3],     smem_u + QK_AHI + a_off + kb);
    ldsm_x4(A[4], A[5], A[6], A[7],     smem_u + QK_AHI + a_off + 16 * ROW_BYTES + kb);
    ldsm_x4(A[8], A[9], A[10], A[11],   smem_u + QK_ALO + a_off + kb);
    ldsm_x4(A[12], A[13], A[14], A[15], smem_u + QK_ALO + a_off + 16 * ROW_BYTES + kb);
    ldsm_x4(B[0], B[1], B[2], B[3],     smem_u + QK_WHI + b_off + kb);
    ldsm_x4(B[4], B[5], B[6], B[7],     smem_u + QK_WHI + b_off + 16 * ROW_BYTES + kb);
    ldsm_x4(B[8], B[9], B[10], B[11],   smem_u + QK_WLO + b_off + kb);
    ldsm_x4(B[12], B[13], B[14], B[15], smem_u + QK_WLO + b_off + 16 * ROW_BYTES + kb);
}

__device__ __forceinline__ void qkv_frag_mma(float acc[2][4][4], const unsigned* A, const unsigned* B) {
#pragma unroll
    for (int ni = 0; ni < 4; ni++)
#pragma unroll
        for (int mi = 0; mi < 2; mi++)
            mma_bf16(acc[mi][ni], A + mi * 4, B[ni * 2], B[ni * 2 + 1]);            // hi*hi
#pragma unroll
    for (int ni = 0; ni < 4; ni++)
#pragma unroll
        for (int mi = 0; mi < 2; mi++)
            mma_bf16(acc[mi][ni], A + mi * 4, B[8 + ni * 2], B[8 + ni * 2 + 1]);    // hi*lo
#pragma unroll
    for (int ni = 0; ni < 4; ni++)
#pragma unroll
        for (int mi = 0; mi < 2; mi++)
            mma_bf16(acc[mi][ni], A + 8 + mi * 4, B[ni * 2], B[ni * 2 + 1]);        // lo*hi
}

// load W tiles into smem (512 threads, 4 threads/row)
__device__ __forceinline__ void qkv_load_w(char* smem, int t, int mode) {
    const __nv_bfloat16* w_hi_g = g_wThi + (size_t)mode * DIM * DIM;
    const __nv_bfloat16* w_lo_g = g_wTlo + (size_t)mode * DIM * DIM;
    int r = t >> 2;
    int c0 = (t & 3) * 32;
    const uint4* wh = (const uint4*)(w_hi_g + (size_t)r * DIM + c0);
    const uint4* wl = (const uint4*)(w_lo_g + (size_t)r * DIM + c0);
    char* dwh = smem + QK_WHI + r * ROW_BYTES + c0 * 2;
    char* dwl = smem + QK_WLO + r * ROW_BYTES + c0 * 2;
#pragma unroll
    for (int i = 0; i < 4; i++) {
        ((uint4*)dwh)[i] = wh[i];
        ((uint4*)dwl)[i] = wl[i];
    }
}

// shared mainloop (A + W in smem) -> acc
__device__ __forceinline__ void qkv_mainloop(unsigned smem_u, unsigned a_off, unsigned b_off,
                                             float acc[2][4][4]) {
#pragma unroll
    for (int mi = 0; mi < 2; mi++)
#pragma unroll
        for (int ni = 0; ni < 4; ni++)
#pragma unroll
            for (int j = 0; j < 4; j++) acc[mi][ni][j] = 0.0f;

    unsigned Af[2][16], Bf[2][16];
    qkv_load_frags(Af[0], Bf[0], smem_u, a_off, b_off, 0);
#pragma unroll
    for (int k0 = 0; k0 < 8; k0++) {
        int cur = k0 & 1;
        if (k0 < 7)
            qkv_load_frags(Af[cur ^ 1], Bf[cur ^ 1], smem_u, a_off, b_off, (unsigned)((k0 + 1) * 32));
        qkv_frag_mma(acc, Af[cur], Bf[cur]);
    }
}

// ================= QKV GEMM (+ bucket fill on blockIdx.y==3) =================
__global__ __launch_bounds__(512, 1) void k_mma_qkv(const float* __restrict__ x,
                                                    const int* __restrict__ ei) {
    if (blockIdx.y == 3) {
        int base = (blockIdx.x * 512 + threadIdx.x) * 4;
#pragma unroll
        for (int i = 0; i < 4; i++) {
            int e = base + i;
            if (e < NEDGES) {
                int src = ei[e];
                int dst = ei[NEDGES + e];
                int pos = atomicAdd(&g_deg[dst], 1);
                g_bucket[dst * MAXDEG + pos] = src;
            }
        }
        return;
    }

    extern __shared__ char smem[];
    unsigned smem_u = (unsigned)__cvta_generic_to_shared(smem);
    int t = threadIdx.x;
    int mode = blockIdx.y;
    int row0 = blockIdx.x * 128;
    float* outp = (mode == 0) ? g_q : (mode == 1) ? g_k : g_v;

    // ---- load + split A tile (128 x 128): 4 threads/row ----
    {
        int r = t >> 2;
        int c0 = (t & 3) * 32;
        int gr = row0 + r;
        char* dsthi = smem + QK_AHI + r * ROW_BYTES + c0 * 2;
        char* dstlo = smem + QK_ALO + r * ROW_BYTES + c0 * 2;
        if (gr < NNODES) {
            const float4* srcp = (const float4*)(x + (size_t)gr * DIM + c0);
#pragma unroll
            for (int i = 0; i < 8; i++) {
                float4 v = srcp[i];
                __nv_bfloat16 hi[4], lo[4];
                hi[0] = __float2bfloat16_rn(v.x); lo[0] = __float2bfloat16_rn(v.x - __bfloat162float(hi[0]));
                hi[1] = __float2bfloat16_rn(v.y); lo[1] = __float2bfloat16_rn(v.y - __bfloat162float(hi[1]));
                hi[2] = __float2bfloat16_rn(v.z); lo[2] = __float2bfloat16_rn(v.z - __bfloat162float(hi[2]));
                hi[3] = __float2bfloat16_rn(v.w); lo[3] = __float2bfloat16_rn(v.w - __bfloat162float(hi[3]));
                ((uint2*)dsthi)[i] = *(uint2*)hi;
                ((uint2*)dstlo)[i] = *(uint2*)lo;
            }
        } else {
            uint2 z = make_uint2(0, 0);
#pragma unroll
            for (int i = 0; i < 8; i++) { ((uint2*)dsthi)[i] = z; ((uint2*)dstlo)[i] = z; }
        }
    }
    qkv_load_w(smem, t, mode);
    __syncthreads();

    int warp = t >> 5;
    int lane = t & 31;
    int g  = lane >> 2;
    int tg = lane & 3;
    int m_base = (warp >> 2) * 32;
    int n_base = (warp & 3) * 32;

    unsigned a_off = (unsigned)((m_base + (lane & 15)) * ROW_BYTES + ((lane >> 4) << 3) * 2);
    unsigned b_off = (unsigned)((n_base + (lane & 7) + ((lane >> 4) << 3)) * ROW_BYTES
                                + (((lane >> 3) & 1) << 3) * 2);

    float acc[2][4][4];
    qkv_mainloop(smem_u, a_off, b_off, acc);

#pragma unroll
    for (int mi = 0; mi < 2; mi++) {
#pragma unroll
        for (int ni = 0; ni < 4; ni++) {
            int c = n_base + ni * 8 + 2 * tg;
            int r0 = row0 + m_base + mi * 16 + g;
            int r1 = r0 + 8;
            if (r0 < NNODES)
                *(float2*)(outp + (size_t)r0 * DIM + c) = make_float2(acc[mi][ni][0], acc[mi][ni][1]);
            if (r1 < NNODES)
                *(float2*)(outp + (size_t)r1 * DIM + c) = make_float2(acc[mi][ni][2], acc[mi][ni][3]);
        }
    }
}

// ================= output GEMM: same geometry, mode-3 epilogue =================
__global__ __launch_bounds__(512, 1) void k_mma_out(const float* __restrict__ x,
                                                    const float* __restrict__ bout,
                                                    float* __restrict__ dout) {
    extern __shared__ char smem[];
    unsigned smem_u = (unsigned)__cvta_generic_to_shared(smem);
    int t = threadIdx.x;
    int row0 = blockIdx.x * 128;

    // ---- A tile: flat copy of pre-split agg (128 x 128), 4 threads/row ----
    {
        int r = t >> 2;
        int c0 = (t & 3) * 32;
        int gr = row0 + r;
        char* dsthi = smem + QK_AHI + r * ROW_BYTES + c0 * 2;
        char* dstlo = smem + QK_ALO + r * ROW_BYTES + c0 * 2;
        if (gr < NNODES) {
            const uint4* sh = (const uint4*)(g_ahi + (size_t)gr * DIM + c0);
            const uint4* sl = (const uint4*)(g_alo + (size_t)gr * DIM + c0);
#pragma unroll
            for (int i = 0; i < 4; i++) {
                ((uint4*)dsthi)[i] = sh[i];
                ((uint4*)dstlo)[i] = sl[i];
            }
        } else {
            uint4 z = make_uint4(0, 0, 0, 0);
#pragma unroll
            for (int i = 0; i < 4; i++) { ((uint4*)dsthi)[i] = z; ((uint4*)dstlo)[i] = z; }
        }
    }
    qkv_load_w(smem, t, 3);
    __syncthreads();

    int warp = t >> 5;
    int lane = t & 31;
    int g  = lane >> 2;
    int tg = lane & 3;
    int m_base = (warp >> 2) * 32;
    int n_base = (warp & 3) * 32;

    unsigned a_off = (unsigned)((m_base + (lane & 15)) * ROW_BYTES + ((lane >> 4) << 3) * 2);
    unsigned b_off = (unsigned)((n_base + (lane & 7) + ((lane >> 4) << 3)) * ROW_BYTES
                                + (((lane >> 3) & 1) << 3) * 2);

    float acc[2][4][4];
    qkv_mainloop(smem_u, a_off, b_off, acc);

#pragma unroll
    for (int mi = 0; mi < 2; mi++) {
#pragma unroll
        for (int ni = 0; ni < 4; ni++) {
            int c = n_base + ni * 8 + 2 * tg;
            int r0 = row0 + m_base + mi * 16 + g;
            int r1 = r0 + 8;
            float2 b = *(const float2*)(bout + c);
            if (r0 < NNODES) {
                float2 xr = *(const float2*)(x + (size_t)r0 * DIM + c);
                float2 v0;
                v0.x = fmaxf(acc[mi][ni][0] + b.x, 0.0f) + xr.x;
                v0.y = fmaxf(acc[mi][ni][1] + b.y, 0.0f) + xr.y;
                *(float2*)(dout + (size_t)r0 * DIM + c) = v0;
            }
            if (r1 < NNODES) {
                float2 xr = *(const float2*)(x + (size_t)r1 * DIM + c);
                float2 v1;
                v1.x = fmaxf(acc[mi][ni][2] + b.x, 0.0f) + xr.x;
                v1.y = fmaxf(acc[mi][ni][3] + b.y, 0.0f) + xr.y;
                *(float2*)(dout + (size_t)r1 * DIM + c) = v1;
            }
        }
    }
}

// ---------------- launch ----------------
extern "C" void kernel_launch(void* const* d_in, const int* in_sizes, int n_in,
                              void* d_out, int out_size) {
    const float* x      = (const float*)d_in[0];
    const int* ei       = (const int*)d_in[1];
    const float* Wt     = (const float*)d_in[2];
    const float* Ws     = (const float*)d_in[3];
    const float* Wc     = (const float*)d_in[4];
    const float* Wout   = (const float*)d_in[5];
    const float* bout   = (const float*)d_in[6];
    float* out          = (float*)d_out;

    static bool configured = false;
    if (!configured) {
        cudaFuncSetAttribute(k_mma_qkv, cudaFuncAttributeMaxDynamicSharedMemorySize, QK_SMEM);
        cudaFuncSetAttribute(k_mma_out, cudaFuncAttributeMaxDynamicSharedMemorySize, QK_SMEM);
        configured = true;
    }

    // 4 launches -> profile slot 3 = k_mma_out (new geometry)
    k_prep<<<256, 256>>>(Wt, Ws, Wc, Wout);                            // 0
    dim3 gq((NNODES + 127) / 128, 4);   // y==3 -> bucket fill
    k_mma_qkv<<<gq, 512, QK_SMEM>>>(x, ei);                            // 1
    k_fused<<<(NNODES * 32 + 255) / 256, 256>>>();                     // 2
    k_mma_out<<<(NNODES + 127) / 128, 512, QK_SMEM>>>(x, bout, out);   // 3 <- profiled
}

// round 16
// speedup vs baseline: 1.1732x; 1.0362x over previous
#include <cuda_runtime.h>
#include <cuda_bf16.h>
#include <cuda_fp16.h>

#define NNODES 50000
#define NEDGES 800000
#define DIM 128
#define NH 4
#define MAXDEG 128

// ---------------- scratch (device globals: no allocs allowed) ----------------
__device__ __align__(16) float g_q[NNODES * DIM];
__device__ __align__(16) float g_k[NNODES * DIM];
__device__ __align__(16) float g_v[NNODES * DIM];

__device__ int g_deg[NNODES];
__device__ int g_bucket[NNODES * MAXDEG];

// agg in fp16 (hi only — out GEMM uses 2-term fp16 split on W side)
__device__ __align__(16) __half g_af16[NNODES * DIM];
// QKV weights: bf16 3-term split, [n][k]
__device__ __align__(16) __nv_bfloat16 g_wThi[3 * DIM * DIM];
__device__ __align__(16) __nv_bfloat16 g_wTlo[3 * DIM * DIM];
// out weights: fp16 2-term split, [n][k]
__device__ __align__(16) __half g_wOhi[DIM * DIM];
__device__ __align__(16) __half g_wOlo[DIM * DIM];

// ---------------- prep: zero degrees + split/transpose weights ----------------
__global__ __launch_bounds__(256) void k_prep(const float* __restrict__ Wt,
                                              const float* __restrict__ Ws,
                                              const float* __restrict__ Wc,
                                              const float* __restrict__ Wout) {
    int t = blockIdx.x * blockDim.x + threadIdx.x;
    if (t < NNODES) g_deg[t] = 0;
    if (t < 4 * DIM * DIM) {
        int w = t >> 14;
        int idx = t & 16383;
        int k = idx >> 7;
        int n = idx & 127;
        if (w < 3) {
            const float* W = (w == 0) ? Wt : (w == 1) ? Ws : Wc;
            float v = W[k * DIM + n];
            __nv_bfloat16 h = __float2bfloat16_rn(v);
            g_wThi[(size_t)w * DIM * DIM + n * DIM + k] = h;
            g_wTlo[(size_t)w * DIM * DIM + n * DIM + k] = __float2bfloat16_rn(v - __bfloat162float(h));
        } else {
            float v = Wout[k * DIM + n];
            __half h = __float2half_rn(v);
            g_wOhi[n * DIM + k] = h;
            g_wOlo[n * DIM + k] = __float2half_rn(v - __half2float(h));
        }
    }
}

// ---------------- fused scores + softmax + aggregation (one warp / dst) ----------------
__global__ __launch_bounds__(256, 5) void k_fused() {
    int n = (blockIdx.x * blockDim.x + threadIdx.x) >> 5;
    if (n >= NNODES) return;
    int l = threadIdx.x & 31;
    int start = n * MAXDEG;
    int deg = g_deg[n];

    float4 qv = *(const float4*)(g_q + (size_t)n * DIM + (l << 2));
    float denom = 0.0f;
    float4 vacc = make_float4(0.f, 0.f, 0.f, 0.f);

    int j = 0;
    for (; j + 3 < deg; j += 4) {
        int s0 = g_bucket[start + j];
        int s1 = g_bucket[start + j + 1];
        int s2 = g_bucket[start + j + 2];
        int s3 = g_bucket[start + j + 3];
        float4 k0 = *(const float4*)(g_k + (size_t)s0 * DIM + (l << 2));
        float4 k1 = *(const float4*)(g_k + (size_t)s1 * DIM + (l << 2));
        float4 k2 = *(const float4*)(g_k + (size_t)s2 * DIM + (l << 2));
        float4 k3 = *(const float4*)(g_k + (size_t)s3 * DIM + (l << 2));
        float4 v0 = *(const float4*)(g_v + (size_t)s0 * DIM + (l << 2));
        float4 v1 = *(const float4*)(g_v + (size_t)s1 * DIM + (l << 2));
        float4 v2 = *(const float4*)(g_v + (size_t)s2 * DIM + (l << 2));
        float4 v3 = *(const float4*)(g_v + (size_t)s3 * DIM + (l << 2));
        float p0 = qv.x * k0.x + qv.y * k0.y + qv.z * k0.z + qv.w * k0.w;
        float p1 = qv.x * k1.x + qv.y * k1.y + qv.z * k1.z + qv.w * k1.w;
        float p2 = qv.x * k2.x + qv.y * k2.y + qv.z * k2.z + qv.w * k2.w;
        float p3 = qv.x * k3.x + qv.y * k3.y + qv.z * k3.z + qv.w * k3.w;
        p0 += __shfl_xor_sync(0xffffffffu, p0, 1);
        p1 += __shfl_xor_sync(0xffffffffu, p1, 1);
        p2 += __shfl_xor_sync(0xffffffffu, p2, 1);
        p3 += __shfl_xor_sync(0xffffffffu, p3, 1);
        p0 += __shfl_xor_sync(0xffffffffu, p0, 2);
        p1 += __shfl_xor_sync(0xffffffffu, p1, 2);
        p2 += __shfl_xor_sync(0xffffffffu, p2, 2);
        p3 += __shfl_xor_sync(0xffffffffu, p3, 2);
        p0 += __shfl_xor_sync(0xffffffffu, p0, 4);
        p1 += __shfl_xor_sync(0xffffffffu, p1, 4);
        p2 += __shfl_xor_sync(0xffffffffu, p2, 4);
        p3 += __shfl_xor_sync(0xffffffffu, p3, 4);
        float e0 = __expf(p0);
        float e1 = __expf(p1);
        float e2 = __expf(p2);
        float e3 = __expf(p3);
        denom += (e0 + e1) + (e2 + e3);
        vacc.x = fmaf(e0, v0.x, fmaf(e1, v1.x, fmaf(e2, v2.x, fmaf(e3, v3.x, vacc.x))));
        vacc.y = fmaf(e0, v0.y, fmaf(e1, v1.y, fmaf(e2, v2.y, fmaf(e3, v3.y, vacc.y))));
        vacc.z = fmaf(e0, v0.z, fmaf(e1, v1.z, fmaf(e2, v2.z, fmaf(e3, v3.z, vacc.z))));
        vacc.w = fmaf(e0, v0.w, fmaf(e1, v1.w, fmaf(e2, v2.w, fmaf(e3, v3.w, vacc.w))));
    }
    for (; j < deg; j++) {
        int s0 = g_bucket[start + j];
        float4 k0 = *(const float4*)(g_k + (size_t)s0 * DIM + (l << 2));
        float4 v0 = *(const float4*)(g_v + (size_t)s0 * DIM + (l << 2));
        float p0 = qv.x * k0.x + qv.y * k0.y + qv.z * k0.z + qv.w * k0.w;
        p0 += __shfl_xor_sync(0xffffffffu, p0, 1);
        p0 += __shfl_xor_sync(0xffffffffu, p0, 2);
        p0 += __shfl_xor_sync(0xffffffffu, p0, 4);
        float e0 = __expf(p0);
        denom += e0;
        vacc.x = fmaf(e0, v0.x, vacc.x);
        vacc.y = fmaf(e0, v0.y, vacc.y);
        vacc.z = fmaf(e0, v0.z, vacc.z);
        vacc.w = fmaf(e0, v0.w, vacc.w);
    }
    float inv = (deg > 0) ? __fdividef(1.0f, denom) : 0.0f;
    __half h[4];
    h[0] = __float2half_rn(vacc.x * inv);
    h[1] = __float2half_rn(vacc.y * inv);
    h[2] = __float2half_rn(vacc.z * inv);
    h[3] = __float2half_rn(vacc.w * inv);
    *(uint2*)(g_af16 + (size_t)n * DIM + (l << 2)) = *(uint2*)h;
}

// ---------------- mma.sync GEMM bits ----------------
#define SMEM_STRIDE 136
#define ROW_BYTES   (SMEM_STRIDE * 2)   // 272 -> LDSM conflict-free (bank step 4)

__device__ __forceinline__ void mma_bf16(float* c, const unsigned* a, unsigned b0, unsigned b1) {
    asm volatile(
        "mma.sync.aligned.m16n8k16.row.col.f32.bf16.bf16.f32 "
        "{%0,%1,%2,%3}, {%4,%5,%6,%7}, {%8,%9}, {%0,%1,%2,%3};"
        : "+f"(c[0]), "+f"(c[1]), "+f"(c[2]), "+f"(c[3])
        : "r"(a[0]), "r"(a[1]), "r"(a[2]), "r"(a[3]), "r"(b0), "r"(b1));
}

__device__ __forceinline__ void mma_f16(float* c, const unsigned* a, unsigned b0, unsigned b1) {
    asm volatile(
        "mma.sync.aligned.m16n8k16.row.col.f32.f16.f16.f32 "
        "{%0,%1,%2,%3}, {%4,%5,%6,%7}, {%8,%9}, {%0,%1,%2,%3};"
        : "+f"(c[0]), "+f"(c[1]), "+f"(c[2]), "+f"(c[3])
        : "r"(a[0]), "r"(a[1]), "r"(a[2]), "r"(a[3]), "r"(b0), "r"(b1));
}

__device__ __forceinline__ void ldsm_x4(unsigned& r0, unsigned& r1, unsigned& r2, unsigned& r3,
                                        unsigned addr) {
    asm volatile("ldmatrix.sync.aligned.m8n8.x4.shared.b16 {%0,%1,%2,%3}, [%4];"
                 : "=r"(r0), "=r"(r1), "=r"(r2), "=r"(r3) : "r"(addr));
}

// ================= QKV GEMM: 128-row CTA tile, 512 threads, warp 32x32 =================
#define QK_AHI 0
#define QK_ALO 34816
#define QK_WHI 69632
#define QK_WLO 104448
#define QK_SMEM 139264

__device__ __forceinline__ void qkv_load_frags(unsigned* A, unsigned* B, unsigned smem_u,
                                               unsigned a_off, unsigned b_off, unsigned kb) {
    ldsm_x4(A[0], A[1], A[2], A[3],     smem_u + QK_AHI + a_off + kb);
    ldsm_x4(A[4], A[5], A[6], A[7],     smem_u + QK_AHI + a_off + 16 * ROW_BYTES + kb);
    ldsm_x4(A[8], A[9], A[10], A[11],   smem_u + QK_ALO + a_off + kb);
    ldsm_x4(A[12], A[13], A[14], A[15], smem_u + QK_ALO + a_off + 16 * ROW_BYTES + kb);
    ldsm_x4(B[0], B[1], B[2], B[3],     smem_u + QK_WHI + b_off + kb);
    ldsm_x4(B[4], B[5], B[6], B[7],     smem_u + QK_WHI + b_off + 16 * ROW_BYTES + kb);
    ldsm_x4(B[8], B[9], B[10], B[11],   smem_u + QK_WLO + b_off + kb);
    ldsm_x4(B[12], B[13], B[14], B[15], smem_u + QK_WLO + b_off + 16 * ROW_BYTES + kb);
}

__device__ __forceinline__ void qkv_frag_mma(float acc[2][4][4], const unsigned* A, const unsigned* B) {
#pragma unroll
    for (int ni = 0; ni < 4; ni++)
#pragma unroll
        for (int mi = 0; mi < 2; mi++)
            mma_bf16(acc[mi][ni], A + mi * 4, B[ni * 2], B[ni * 2 + 1]);            // hi*hi
#pragma unroll
    for (int ni = 0; ni < 4; ni++)
#pragma unroll
        for (int mi = 0; mi < 2; mi++)
            mma_bf16(acc[mi][ni], A + mi * 4, B[8 + ni * 2], B[8 + ni * 2 + 1]);    // hi*lo
#pragma unroll
    for (int ni = 0; ni < 4; ni++)
#pragma unroll
        for (int mi = 0; mi < 2; mi++)
            mma_bf16(acc[mi][ni], A + 8 + mi * 4, B[ni * 2], B[ni * 2 + 1]);        // lo*hi
}

__global__ __launch_bounds__(512, 1) void k_mma_qkv(const float* __restrict__ x,
                                                    const int* __restrict__ ei) {
    if (blockIdx.y == 3) {
        int base = (blockIdx.x * 512 + threadIdx.x) * 4;
#pragma unroll
        for (int i = 0; i < 4; i++) {
            int e = base + i;
            if (e < NEDGES) {
                int src = ei[e];
                int dst = ei[NEDGES + e];
                int pos = atomicAdd(&g_deg[dst], 1);
                g_bucket[dst * MAXDEG + pos] = src;
            }
        }
        return;
    }

    extern __shared__ char smem[];
    unsigned smem_u = (unsigned)__cvta_generic_to_shared(smem);
    int t = threadIdx.x;
    int mode = blockIdx.y;
    int row0 = blockIdx.x * 128;
    float* outp = (mode == 0) ? g_q : (mode == 1) ? g_k : g_v;

    // ---- load + split A tile (128 x 128): 4 threads/row ----
    {
        int r = t >> 2;
        int c0 = (t & 3) * 32;
        int gr = row0 + r;
        char* dsthi = smem + QK_AHI + r * ROW_BYTES + c0 * 2;
        char* dstlo = smem + QK_ALO + r * ROW_BYTES + c0 * 2;
        if (gr < NNODES) {
            const float4* srcp = (const float4*)(x + (size_t)gr * DIM + c0);
#pragma unroll
            for (int i = 0; i < 8; i++) {
                float4 v = srcp[i];
                __nv_bfloat16 hi[4], lo[4];
                hi[0] = __float2bfloat16_rn(v.x); lo[0] = __float2bfloat16_rn(v.x - __bfloat162float(hi[0]));
                hi[1] = __float2bfloat16_rn(v.y); lo[1] = __float2bfloat16_rn(v.y - __bfloat162float(hi[1]));
                hi[2] = __float2bfloat16_rn(v.z); lo[2] = __float2bfloat16_rn(v.z - __bfloat162float(hi[2]));
                hi[3] = __float2bfloat16_rn(v.w); lo[3] = __float2bfloat16_rn(v.w - __bfloat162float(hi[3]));
                ((uint2*)dsthi)[i] = *(uint2*)hi;
                ((uint2*)dstlo)[i] = *(uint2*)lo;
            }
        } else {
            uint2 z = make_uint2(0, 0);
#pragma unroll
            for (int i = 0; i < 8; i++) { ((uint2*)dsthi)[i] = z; ((uint2*)dstlo)[i] = z; }
        }
    }
    // ---- W tiles (bf16 hi/lo, [n][k]): 4 threads/row ----
    {
        const __nv_bfloat16* w_hi_g = g_wThi + (size_t)mode * DIM * DIM;
        const __nv_bfloat16* w_lo_g = g_wTlo + (size_t)mode * DIM * DIM;
        int r = t >> 2;
        int c0 = (t & 3) * 32;
        const uint4* wh = (const uint4*)(w_hi_g + (size_t)r * DIM + c0);
        const uint4* wl = (const uint4*)(w_lo_g + (size_t)r * DIM + c0);
        char* dwh = smem + QK_WHI + r * ROW_BYTES + c0 * 2;
        char* dwl = smem + QK_WLO + r * ROW_BYTES + c0 * 2;
#pragma unroll
        for (int i = 0; i < 4; i++) {
            ((uint4*)dwh)[i] = wh[i];
            ((uint4*)dwl)[i] = wl[i];
        }
    }
    __syncthreads();

    int warp = t >> 5;
    int lane = t & 31;
    int g  = lane >> 2;
    int tg = lane & 3;
    int m_base = (warp >> 2) * 32;
    int n_base = (warp & 3) * 32;

    unsigned a_off = (unsigned)((m_base + (lane & 15)) * ROW_BYTES + ((lane >> 4) << 3) * 2);
    unsigned b_off = (unsigned)((n_base + (lane & 7) + ((lane >> 4) << 3)) * ROW_BYTES
                                + (((lane >> 3) & 1) << 3) * 2);

    float acc[2][4][4];
#pragma unroll
    for (int mi = 0; mi < 2; mi++)
#pragma unroll
        for (int ni = 0; ni < 4; ni++)
#pragma unroll
            for (int j = 0; j < 4; j++) acc[mi][ni][j] = 0.0f;

    unsigned Af[2][16], Bf[2][16];
    qkv_load_frags(Af[0], Bf[0], smem_u, a_off, b_off, 0);
#pragma unroll
    for (int k0 = 0; k0 < 8; k0++) {
        int cur = k0 & 1;
        if (k0 < 7)
            qkv_load_frags(Af[cur ^ 1], Bf[cur ^ 1], smem_u, a_off, b_off, (unsigned)((k0 + 1) * 32));
        qkv_frag_mma(acc, Af[cur], Bf[cur]);
    }

#pragma unroll
    for (int mi = 0; mi < 2; mi++) {
#pragma unroll
        for (int ni = 0; ni < 4; ni++) {
            int c = n_base + ni * 8 + 2 * tg;
            int r0 = row0 + m_base + mi * 16 + g;
            int r1 = r0 + 8;
            if (r0 < NNODES)
                *(float2*)(outp + (size_t)r0 * DIM + c) = make_float2(acc[mi][ni][0], acc[mi][ni][1]);
            if (r1 < NNODES)
                *(float2*)(outp + (size_t)r1 * DIM + c) = make_float2(acc[mi][ni][2], acc[mi][ni][3]);
        }
    }
}

// ================= output GEMM: fp16 2-term (Ahi*Bhi + Ahi*Blo), A-hi only =================
#define O_AHI 0
#define O_WHI 34816
#define O_WLO 69632
#define O_SMEM 104448

__global__ __launch_bounds__(512, 1) void k_mma_out(const float* __restrict__ x,
                                                    const float* __restrict__ bout,
                                                    float* __restrict__ dout) {
    extern __shared__ char smem[];
    unsigned smem_u = (unsigned)__cvta_generic_to_shared(smem);
    int t = threadIdx.x;
    int row0 = blockIdx.x * 128;

    // ---- A tile: fp16 agg (128 x 128), 4 threads/row ----
    {
        int r = t >> 2;
        int c0 = (t & 3) * 32;
        int gr = row0 + r;
        char* dst = smem + O_AHI + r * ROW_BYTES + c0 * 2;
        if (gr < NNODES) {
            const uint4* sh = (const uint4*)(g_af16 + (size_t)gr * DIM + c0);
#pragma unroll
            for (int i = 0; i < 4; i++) ((uint4*)dst)[i] = sh[i];
        } else {
            uint4 z = make_uint4(0, 0, 0, 0);
#pragma unroll
            for (int i = 0; i < 4; i++) ((uint4*)dst)[i] = z;
        }
    }
    // ---- W tiles (fp16 hi/lo, [n][k]): 4 threads/row ----
    {
        int r = t >> 2;
        int c0 = (t & 3) * 32;
        const uint4* wh = (const uint4*)(g_wOhi + (size_t)r * DIM + c0);
        const uint4* wl = (const uint4*)(g_wOlo + (size_t)r * DIM + c0);
        char* dwh = smem + O_WHI + r * ROW_BYTES + c0 * 2;
        char* dwl = smem + O_WLO + r * ROW_BYTES + c0 * 2;
#pragma unroll
        for (int i = 0; i < 4; i++) {
            ((uint4*)dwh)[i] = wh[i];
            ((uint4*)dwl)[i] = wl[i];
        }
    }
    __syncthreads();

    int warp = t >> 5;
    int lane = t & 31;
    int g  = lane >> 2;
    int tg = lane & 3;
    int m_base = (warp >> 2) * 32;
    int n_base = (warp & 3) * 32;

    unsigned a_off = (unsigned)((m_base + (lane & 15)) * ROW_BYTES + ((lane >> 4) << 3) * 2);
    unsigned b_off = (unsigned)((n_base + (lane & 7) + ((lane >> 4) << 3)) * ROW_BYTES
                                + (((lane >> 3) & 1) << 3) * 2);

    float acc[2][4][4];
#pragma unroll
    for (int mi = 0; mi < 2; mi++)
#pragma unroll
        for (int ni = 0; ni < 4; ni++)
#pragma unroll
            for (int j = 0; j < 4; j++) acc[mi][ni][j] = 0.0f;

    unsigned Af[2][8], Bf[2][16];
    // prologue load k0
    ldsm_x4(Af[0][0], Af[0][1], Af[0][2], Af[0][3], smem_u + O_AHI + a_off);
    ldsm_x4(Af[0][4], Af[0][5], Af[0][6], Af[0][7], smem_u + O_AHI + a_off + 16 * ROW_BYTES);
    ldsm_x4(Bf[0][0], Bf[0][1], Bf[0][2], Bf[0][3],     smem_u + O_WHI + b_off);
    ldsm_x4(Bf[0][4], Bf[0][5], Bf[0][6], Bf[0][7],     smem_u + O_WHI + b_off + 16 * ROW_BYTES);
    ldsm_x4(Bf[0][8], Bf[0][9], Bf[0][10], Bf[0][11],   smem_u + O_WLO + b_off);
    ldsm_x4(Bf[0][12], Bf[0][13], Bf[0][14], Bf[0][15], smem_u + O_WLO + b_off + 16 * ROW_BYTES);
#pragma unroll
    for (int k0 = 0; k0 < 8; k0++) {
        int cur = k0 & 1;
        int nxt = cur ^ 1;
        if (k0 < 7) {
            unsigned kb = (unsigned)((k0 + 1) * 32);
            ldsm_x4(Af[nxt][0], Af[nxt][1], Af[nxt][2], Af[nxt][3], smem_u + O_AHI + a_off + kb);
            ldsm_x4(Af[nxt][4], Af[nxt][5], Af[nxt][6], Af[nxt][7], smem_u + O_AHI + a_off + 16 * ROW_BYTES + kb);
            ldsm_x4(Bf[nxt][0], Bf[nxt][1], Bf[nxt][2], Bf[nxt][3],     smem_u + O_WHI + b_off + kb);
            ldsm_x4(Bf[nxt][4], Bf[nxt][5], Bf[nxt][6], Bf[nxt][7],     smem_u + O_WHI + b_off + 16 * ROW_BYTES + kb);
            ldsm_x4(Bf[nxt][8], Bf[nxt][9], Bf[nxt][10], Bf[nxt][11],   smem_u + O_WLO + b_off + kb);
            ldsm_x4(Bf[nxt][12], Bf[nxt][13], Bf[nxt][14], Bf[nxt][15], smem_u + O_WLO + b_off + 16 * ROW_BYTES + kb);
        }
#pragma unroll
        for (int ni = 0; ni < 4; ni++)
#pragma unroll
            for (int mi = 0; mi < 2; mi++)
                mma_f16(acc[mi][ni], Af[cur] + mi * 4, Bf[cur][ni * 2], Bf[cur][ni * 2 + 1]);      // hi*hi
#pragma unroll
        for (int ni = 0; ni < 4; ni++)
#pragma unroll
            for (int mi = 0; mi < 2; mi++)
                mma_f16(acc[mi][ni], Af[cur] + mi * 4, Bf[cur][8 + ni * 2], Bf[cur][8 + ni * 2 + 1]); // hi*lo
    }

#pragma unroll
    for (int mi = 0; mi < 2; mi++) {
#pragma unroll
        for (int ni = 0; ni < 4; ni++) {
            int c = n_base + ni * 8 + 2 * tg;
            int r0 = row0 + m_base + mi * 16 + g;
            int r1 = r0 + 8;
            float2 b = *(const float2*)(bout + c);
            if (r0 < NNODES) {
                float2 xr = *(const float2*)(x + (size_t)r0 * DIM + c);
                float2 v0;
                v0.x = fmaxf(acc[mi][ni][0] + b.x, 0.0f) + xr.x;
                v0.y = fmaxf(acc[mi][ni][1] + b.y, 0.0f) + xr.y;
                *(float2*)(dout + (size_t)r0 * DIM + c) = v0;
            }
            if (r1 < NNODES) {
                float2 xr = *(const float2*)(x + (size_t)r1 * DIM + c);
                float2 v1;
                v1.x = fmaxf(acc[mi][ni][2] + b.x, 0.0f) + xr.x;
                v1.y = fmaxf(acc[mi][ni][3] + b.y, 0.0f) + xr.y;
                *(float2*)(dout + (size_t)r1 * DIM + c) = v1;
            }
        }
    }
}

// ---------------- launch ----------------
extern "C" void kernel_launch(void* const* d_in, const int* in_sizes, int n_in,
                              void* d_out, int out_size) {
    const float* x      = (const float*)d_in[0];
    const int* ei       = (const int*)d_in[1];
    const float* Wt     = (const float*)d_in[2];
    const float* Ws     = (const float*)d_in[3];
    const float* Wc     = (const float*)d_in[4];
    const float* Wout   = (const float*)d_in[5];
    const float* bout   = (const float*)d_in[6];
    float* out          = (float*)d_out;

    static bool configured = false;
    if (!configured) {
        cudaFuncSetAttribute(k_mma_qkv, cudaFuncAttributeMaxDynamicSharedMemorySize, QK_SMEM);
        cudaFuncSetAttribute(k_mma_out, cudaFuncAttributeMaxDynamicSharedMemorySize, O_SMEM);
        configured = true;
    }

    // 4 launches -> profile slot 3 = k_mma_out (fp16 2-term)
    k_prep<<<256, 256>>>(Wt, Ws, Wc, Wout);                            // 0
    dim3 gq((NNODES + 127) / 128, 4);   // y==3 -> bucket fill
    k_mma_qkv<<<gq, 512, QK_SMEM>>>(x, ei);                            // 1
    k_fused<<<(NNODES * 32 + 255) / 256, 256>>>();                     // 2
    k_mma_out<<<(NNODES + 127) / 128, 512, O_SMEM>>>(x, bout, out);    // 3 <- profiled
}